// round 14
// baseline (speedup 1.0000x reference)
#include <cuda_runtime.h>
#include <cuda_fp16.h>
#include <math.h>
#include <stdint.h>

#define Bb  2
#define Ss  2048
#define Hh  1024
#define NHh 16
#define HDd 64
#define Mtot (Bb * Ss)          // 4096

// ---------------- scratch planes (__device__ globals; no allocs) -----------
__device__ __half g_Xh[(size_t)Mtot * Hh];            // fp16-rounded X
__device__ __half g_Wh[4][(size_t)Hh * Hh];           // transposed weights hi
__device__ __half g_Wl[(size_t)Hh * Hh];              // o_w lo plane only
__device__ __half g_Qh[(size_t)Bb * NHh * Ss * HDd];  // Q hi (gain folded)
__device__ __half g_Kh[(size_t)Bb * NHh * Ss * HDd];
__device__ __half g_Vh[(size_t)Bb * NHh * Ss * HDd];  // V fp16 (pre-rounded)
__device__ __half g_VTh[(size_t)Bb * NHh * HDd * Ss];
__device__ __half g_Ph[(size_t)Bb * NHh * Ss * Ss];   // prob hi plane (pad stays 0)
__device__ __half g_Ch[(size_t)Mtot * Hh];            // fp16 ctx
__device__ float  g_gain[(size_t)Bb * Ss * NHh];

// ---------------- helpers ---------------------------------------------------
__device__ __forceinline__ uint32_t smem_u32(const void* p) {
    uint32_t a;
    asm("{ .reg .u64 t; cvta.to.shared.u64 t, %1; cvt.u32.u64 %0, t; }" : "=r"(a) : "l"(p));
    return a;
}
__device__ __forceinline__ void split_f(float x, __half& h, __half& l) {
    h = __float2half_rn(x);
    l = __float2half_rn(x - __half2float(h));
}
__device__ __forceinline__ void ldsm4(uint32_t* r, uint32_t addr) {
    asm volatile("ldmatrix.sync.aligned.m8n8.x4.shared.b16 {%0,%1,%2,%3}, [%4];"
        : "=r"(r[0]), "=r"(r[1]), "=r"(r[2]), "=r"(r[3]) : "r"(addr));
}
__device__ __forceinline__ void mma16(float* c, const uint32_t* a, const uint32_t* b) {
    asm volatile("mma.sync.aligned.m16n8k16.row.col.f32.f16.f16.f32 "
        "{%0,%1,%2,%3},{%4,%5,%6,%7},{%8,%9},{%0,%1,%2,%3};"
        : "+f"(c[0]), "+f"(c[1]), "+f"(c[2]), "+f"(c[3])
        : "r"(a[0]), "r"(a[1]), "r"(a[2]), "r"(a[3]), "r"(b[0]), "r"(b[1]));
}
__device__ __forceinline__ void cpa16(uint32_t dst, const void* src) {
    asm volatile("cp.async.cg.shared.global [%0], [%1], 16;" :: "r"(dst), "l"(src));
}
template<int N>
__device__ __forceinline__ void cp_wait() {
    asm volatile("cp.async.wait_group %0;" :: "n"(N < 0 ? 0 : N));
}

// ---------------------------------------------------------------------------
// Split-fp16 tensor-core mainloop.
// AP/BP = #planes A/B. KS = 64-half k-subchunks per stage (BK = KS*64).
// NS = pipeline stages, ONE __syncthreads per k-chunk.
// C[128 x BN] += A[128 x KS*64*nkc] @ Bt[BN x KS*64*nkc]^T, K-major planes.
// 8 warps: 4 M x 2 N; warp tile = 32 x (BN/2).
// ---------------------------------------------------------------------------
template<int BN, int AP, int BP, int NS, int KS>
__device__ __forceinline__ void split_mainloop(
    const __half* __restrict__ Ah, const __half* __restrict__ Al, int ldA,
    const __half* __restrict__ Bh, const __half* __restrict__ Bl, int ldB,
    int nkc, char* smem, float (*cacc)[4])
{
    constexpr int NT = BN / 16;
    constexpr int LROW = KS * 128;          // bytes per tile row
    constexpr int APL = 128 * LROW;         // bytes per A plane
    constexpr int BPL = BN * LROW;          // bytes per B plane
    constexpr int BUF = AP * APL + BP * BPL;

    const int tid = threadIdx.x, lane = tid & 31, wid = tid >> 5;
    const int m_base = (wid & 3) * 32;
    const int n_base = (wid >> 2) * (BN / 2);
    uint32_t sbase = smem_u32(smem);

    auto swoff = [](int row, int ch) -> uint32_t {
        return (uint32_t)row * LROW + ((ch >> 3) << 7) + (((ch & 7) ^ (row & 7)) << 4);
    };

    auto load = [&](int kc, int b) {
        uint32_t s0 = sbase + b * BUF;
        for (int idx = tid; idx < 128 * 8 * KS; idx += 256) {
            int row = idx / (8 * KS), ch = idx % (8 * KS);
            uint32_t off = swoff(row, ch);
            const __half* src = Ah + (size_t)row * ldA + kc * (KS * 64) + ch * 8;
            cpa16(s0 + off, src);
            if (AP == 2)
                cpa16(s0 + APL + off, Al + (size_t)row * ldA + kc * (KS * 64) + ch * 8);
        }
        for (int idx = tid; idx < BN * 8 * KS; idx += 256) {
            int row = idx / (8 * KS), ch = idx % (8 * KS);
            uint32_t off = swoff(row, ch);
            cpa16(s0 + AP * APL + off, Bh + (size_t)row * ldB + kc * (KS * 64) + ch * 8);
            if (BP == 2)
                cpa16(s0 + AP * APL + BPL + off,
                      Bl + (size_t)row * ldB + kc * (KS * 64) + ch * 8);
        }
        asm volatile("cp.async.commit_group;");
    };

#pragma unroll
    for (int s = 0; s < NS - 1; s++)
        if (s < nkc) load(s, s);

    for (int kc = 0; kc < nkc; kc++) {
        int b = kc % NS;
        if (kc + NS - 1 < nkc) cp_wait<NS - 2>();
        else                   cp_wait<0>();
        __syncthreads();
        if (kc + NS - 1 < nkc) load(kc + NS - 1, (kc + NS - 1) % NS);
        uint32_t s0 = sbase + b * BUF;
#pragma unroll
        for (int ks = 0; ks < 4 * KS; ks++) {
            uint32_t a[AP][2][4];
            {
                int row = m_base + (lane & 7) + ((lane >> 3) & 1) * 8;
                int ch  = ks * 2 + (lane >> 4);
#pragma unroll
                for (int mt = 0; mt < 2; mt++) {
                    int r2 = row + mt * 16;
                    uint32_t off = swoff(r2, ch);
                    ldsm4(a[0][mt], s0 + off);
                    if (AP == 2) ldsm4(a[1][mt], s0 + APL + off);
                }
            }
            uint32_t bf[BP][NT][2];
            {
                int row = n_base + (lane & 7) + ((lane >> 4) << 3);
                int ch  = ks * 2 + ((lane >> 3) & 1);
#pragma unroll
                for (int np = 0; np < NT / 2; np++) {
                    int r2 = row + np * 16;
                    uint32_t off = swoff(r2, ch);
                    uint32_t t[4];
                    ldsm4(t, s0 + AP * APL + off);
                    bf[0][2 * np][0] = t[0]; bf[0][2 * np][1] = t[1];
                    bf[0][2 * np + 1][0] = t[2]; bf[0][2 * np + 1][1] = t[3];
                    if (BP == 2) {
                        ldsm4(t, s0 + AP * APL + BPL + off);
                        bf[1][2 * np][0] = t[0]; bf[1][2 * np][1] = t[1];
                        bf[1][2 * np + 1][0] = t[2]; bf[1][2 * np + 1][1] = t[3];
                    }
                }
            }
#pragma unroll
            for (int mt = 0; mt < 2; mt++)
#pragma unroll
                for (int nt = 0; nt < NT; nt++) {
                    float* c = cacc[mt * NT + nt];
                    mma16(c, a[0][mt], bf[0][nt]);
                    if (BP == 2) mma16(c, a[0][mt], bf[1][nt]);
                    if (AP == 2) mma16(c, a[1][mt], bf[0][nt]);
                }
        }
    }
}

#define SMEM_QKV (3 * (128 * 128 + 128 * 128))        // 96 KB  (KS=1,B1,NS=3)
#define SMEM_OUT (2 * (128 * 128 + 2 * 128 * 128))    // 96 KB  (KS=1,B2,NS=2)
#define SMEM_SC  (128 * 128 + 128 * 128)              // 32 KB  (KS=1,B1,nkc=1)
#define SMEM_PV  (2 * (128 * 256 + 64 * 256))         // 96 KB  (KS=2,B1,NS=2)

// ---------------------------------------------------------------------------
// QKV projection (z selects Q/K/V). BM=128, BN=128 (two heads per block).
// Plain fp16 GEMM. Q gain folded; V emits fp16 (pre-rounded, same as old vt).
// ---------------------------------------------------------------------------
__global__ __launch_bounds__(256, 2) void gemm_qkv(
    const float* __restrict__ bq, const float* __restrict__ bk,
    const float* __restrict__ bv)
{
    extern __shared__ char smem[];
    const int z = blockIdx.z;
    const int n0 = blockIdx.x * 128, m0 = blockIdx.y * 128;
    const float* bias = (z == 0) ? bq : (z == 1) ? bk : bv;

    float c[16][4];
#pragma unroll
    for (int i = 0; i < 16; i++)
#pragma unroll
        for (int j = 0; j < 4; j++) c[i][j] = 0.f;

    split_mainloop<128, 1, 1, 3, 1>(g_Xh + (size_t)m0 * Hh, nullptr, Hh,
                                    g_Wh[z] + (size_t)n0 * Hh, nullptr, Hh,
                                    16, smem, c);

    const int lane = threadIdx.x & 31, wid = threadIdx.x >> 5;
    const int g = lane >> 2, t = lane & 3;
    const int m_base = (wid & 3) * 32, n_base = (wid >> 2) * 64;
#pragma unroll
    for (int mt = 0; mt < 2; mt++)
#pragma unroll
        for (int nt = 0; nt < 8; nt++)
#pragma unroll
            for (int half = 0; half < 2; half++) {
                int m = m0 + m_base + mt * 16 + g + half * 8;
                int n = n0 + n_base + nt * 8 + 2 * t;
                float vx = c[mt * 8 + nt][half * 2 + 0] + bias[n];
                float vy = c[mt * 8 + nt][half * 2 + 1] + bias[n + 1];
                int h = n >> 6, d = n & 63;
                int bidx = m >> 11, srow = m & (Ss - 1);
                size_t base = (((size_t)(bidx * NHh + h)) * Ss + srow) * HDd + d;
                if (z == 0) {
                    float gs = g_gain[(size_t)m * NHh + h];
                    vx *= gs; vy *= gs;
                }
                __half2 hv = __halves2half2(__float2half_rn(vx), __float2half_rn(vy));
                __half* dst = (z == 0) ? g_Qh : (z == 1) ? g_Kh : g_Vh;
                *(__half2*)(dst + base) = hv;
            }
}

// ---------------------------------------------------------------------------
// Output projection: fp16 ctx @ o_w + o_b -> d_out[:B*S*H] (fp32). 2 MMAs.
// ---------------------------------------------------------------------------
__global__ __launch_bounds__(256, 2) void gemm_out(
    const float* __restrict__ bias, float* __restrict__ out)
{
    extern __shared__ char smem[];
    const int n0 = blockIdx.x * 128, m0 = blockIdx.y * 128;

    float c[16][4];
#pragma unroll
    for (int i = 0; i < 16; i++)
#pragma unroll
        for (int j = 0; j < 4; j++) c[i][j] = 0.f;

    split_mainloop<128, 1, 2, 2, 1>(g_Ch + (size_t)m0 * Hh, nullptr, Hh,
                                    g_Wh[3] + (size_t)n0 * Hh, g_Wl + (size_t)n0 * Hh, Hh,
                                    16, smem, c);

    const int lane = threadIdx.x & 31, wid = threadIdx.x >> 5;
    const int g = lane >> 2, t = lane & 3;
    const int m_base = (wid & 3) * 32, n_base = (wid >> 2) * 64;
#pragma unroll
    for (int mt = 0; mt < 2; mt++)
#pragma unroll
        for (int nt = 0; nt < 8; nt++)
#pragma unroll
            for (int half = 0; half < 2; half++) {
                int m = m0 + m_base + mt * 16 + g + half * 8;
                int n = n0 + n_base + nt * 8 + 2 * t;
                float2 v = make_float2(c[mt * 8 + nt][half * 2] + bias[n],
                                       c[mt * 8 + nt][half * 2 + 1] + bias[n + 1]);
                *(float2*)(out + (size_t)m * Hh + n) = v;
            }
}

// ---------------------------------------------------------------------------
// Scores: 128 q-rows x 128 k-cols per block; 1-MMA (Qh*Kh).
// ---------------------------------------------------------------------------
__global__ __launch_bounds__(256, 2) void scores_mma(float* __restrict__ attn)
{
    extern __shared__ char smem[];
    const int kt = blockIdx.x, qt = blockIdx.y, bh = blockIdx.z;
    const int q0 = qt * 128, k0 = kt * 128;
    float* abase = attn + (size_t)bh * Ss * Ss;

    if (kt > qt) {
        float4 z4 = make_float4(0.f, 0.f, 0.f, 0.f);
        for (int idx = threadIdx.x; idx < 128 * 32; idx += 256) {
            int row = idx >> 5, cc = idx & 31;
            *(float4*)(abase + (size_t)(q0 + row) * Ss + k0 + cc * 4) = z4;
        }
        return;
    }

    float c[16][4];
#pragma unroll
    for (int i = 0; i < 16; i++)
#pragma unroll
        for (int j = 0; j < 4; j++) c[i][j] = 0.f;

    size_t qoff = ((size_t)bh * Ss + q0) * HDd;
    size_t koff = ((size_t)bh * Ss + k0) * HDd;
    split_mainloop<128, 1, 1, 2, 1>(g_Qh + qoff, nullptr, HDd,
                                    g_Kh + koff, nullptr, HDd, 1, smem, c);

    const int lane = threadIdx.x & 31, wid = threadIdx.x >> 5;
    const int g = lane >> 2, t = lane & 3;
    const int m_base = (wid & 3) * 32, n_base = (wid >> 2) * 64;
    const bool diag = (kt == qt);
#pragma unroll
    for (int mt = 0; mt < 2; mt++)
#pragma unroll
        for (int nt = 0; nt < 8; nt++)
#pragma unroll
            for (int half = 0; half < 2; half++) {
                int gi = q0 + m_base + mt * 16 + g + half * 8;
                int gj = k0 + n_base + nt * 8 + 2 * t;
                float vx = c[mt * 8 + nt][half * 2];
                float vy = c[mt * 8 + nt][half * 2 + 1];
                if (diag) {
                    if (gj > gi) vx = 0.f;
                    if (gj + 1 > gi) vy = 0.f;
                }
                *(float2*)(abase + (size_t)gi * Ss + gj) = make_float2(vx, vy);
            }
}

// ---------------------------------------------------------------------------
// Softmax, causal-balanced: block bx handles rows bx and Ss-1-bx, each by a
// 128-thread group -> every block processes exactly Ss+1 elements.
// Writes fp32 weights (d_out) + fp16 prob plane.
// ---------------------------------------------------------------------------
__global__ __launch_bounds__(256) void softmax_kernel(float* __restrict__ attn)
{
    const int bx = blockIdx.x, h = blockIdx.y, b = blockIdx.z;
    const int sub = threadIdx.x >> 7;          // 0 or 1
    const int stid = threadIdx.x & 127;
    const int i = sub ? (Ss - 1 - bx) : bx;
    size_t roff = ((size_t)(b * NHh + h) * Ss + i) * Ss;
    float* row = attn + roff;
    __half* prh = g_Ph + roff;
    const int n = i + 1;
    const int n4 = n & ~3;
    const int tail = n - n4;
    const int lane = stid & 31, wrp = stid >> 5;   // wrp 0..3

    float vals[17];
    int cnt = 0;
    float mx = -INFINITY;
    for (int j = stid * 4; j < n4; j += 512) {
        float4 v = *(const float4*)(row + j);
        vals[cnt++] = v.x; vals[cnt++] = v.y; vals[cnt++] = v.z; vals[cnt++] = v.w;
        mx = fmaxf(mx, fmaxf(fmaxf(v.x, v.y), fmaxf(v.z, v.w)));
    }
    if (stid < tail) {
        float s = row[n4 + stid];
        vals[cnt++] = s;
        mx = fmaxf(mx, s);
    }

#pragma unroll
    for (int o = 16; o; o >>= 1) mx = fmaxf(mx, __shfl_xor_sync(0xffffffffu, mx, o));
    __shared__ float rmax[2][4], rsum[2][4];
    if (lane == 0) rmax[sub][wrp] = mx;
    __syncthreads();
    mx = fmaxf(fmaxf(rmax[sub][0], rmax[sub][1]), fmaxf(rmax[sub][2], rmax[sub][3]));

    float sum = 0.f;
    for (int c2 = 0; c2 < cnt; c2++) {
        vals[c2] = __expf(vals[c2] - mx);
        sum += vals[c2];
    }
#pragma unroll
    for (int o = 16; o; o >>= 1) sum += __shfl_xor_sync(0xffffffffu, sum, o);
    if (lane == 0) rsum[sub][wrp] = sum;
    __syncthreads();
    sum = rsum[sub][0] + rsum[sub][1] + rsum[sub][2] + rsum[sub][3];
    float inv = 1.0f / sum;

    cnt = 0;
    for (int j = stid * 4; j < n4; j += 512) {
        float4 v;
        v.x = vals[cnt++] * inv; v.y = vals[cnt++] * inv;
        v.z = vals[cnt++] * inv; v.w = vals[cnt++] * inv;
        *(float4*)(row + j) = v;
        *(__half2*)(prh + j)     = __halves2half2(__float2half_rn(v.x), __float2half_rn(v.y));
        *(__half2*)(prh + j + 2) = __halves2half2(__float2half_rn(v.z), __float2half_rn(v.w));
    }
    if (stid < tail) {
        float p = vals[cnt++] * inv;
        row[n4 + stid] = p;
        prh[n4 + stid] = __float2half_rn(p);
    }
}

// ---------------------------------------------------------------------------
// V transpose: g_Vh[bh][s][d] -> VTh[bh][d][s] (fp16, values pre-rounded)
// ---------------------------------------------------------------------------
__global__ __launch_bounds__(256) void vt_kernel()
{
    int bh = blockIdx.z;
    const __half* V = g_Vh + (size_t)bh * Ss * HDd;
    __half* VTh = g_VTh + (size_t)bh * HDd * Ss;
    __shared__ __half t[32][33];
    int s0 = blockIdx.x * 32, d0 = blockIdx.y * 32;
    int tx = threadIdx.x & 31, ty = threadIdx.x >> 5;
#pragma unroll
    for (int i = 0; i < 4; i++)
        t[ty + i * 8][tx] = V[(size_t)(s0 + ty + i * 8) * HDd + d0 + tx];
    __syncthreads();
#pragma unroll
    for (int i = 0; i < 4; i++)
        VTh[(size_t)(d0 + ty + i * 8) * Ss + s0 + tx] = t[tx][ty + i * 8];
}

// ---------------------------------------------------------------------------
// PV: ctx = probs @ V (causal). KS=2 (BK=128) halves chunk-loop overhead.
// ---------------------------------------------------------------------------
__global__ __launch_bounds__(256, 2) void pv_mma()
{
    extern __shared__ char smem[];
    const int qt = blockIdx.x, bh = blockIdx.y;
    const int q0 = qt * 128;
    const int b = bh >> 4, h = bh & 15;

    float c[8][4];
#pragma unroll
    for (int i = 0; i < 8; i++)
#pragma unroll
        for (int j = 0; j < 4; j++) c[i][j] = 0.f;

    size_t poff = ((size_t)bh * Ss + q0) * Ss;
    size_t voff = (size_t)bh * HDd * Ss;
    split_mainloop<64, 1, 1, 2, 2>(g_Ph + poff, nullptr, Ss,
                                   g_VTh + voff, nullptr, Ss,
                                   qt + 1, smem, c);

    const int lane = threadIdx.x & 31, wid = threadIdx.x >> 5;
    const int g = lane >> 2, t = lane & 3;
    const int m_base = (wid & 3) * 32, n_base = (wid >> 2) * 32;
#pragma unroll
    for (int mt = 0; mt < 2; mt++)
#pragma unroll
        for (int nt = 0; nt < 4; nt++)
#pragma unroll
            for (int half = 0; half < 2; half++) {
                int m = q0 + m_base + mt * 16 + g + half * 8;
                int d = n_base + nt * 8 + 2 * t;
                __half hx = __float2half_rn(c[mt * 4 + nt][half * 2]);
                __half hy = __float2half_rn(c[mt * 4 + nt][half * 2 + 1]);
                size_t base = ((size_t)b * Ss + m) * Hh + h * 64 + d;
                *(__half2*)(g_Ch + base) = __halves2half2(hx, hy);
            }
}

// ---------------------------------------------------------------------------
// Prep: X fp16 plane; weight transpose (+ lo plane for o_w only).
// ---------------------------------------------------------------------------
__global__ __launch_bounds__(256) void x_conv(const float* __restrict__ hs)
{
    size_t i = ((size_t)blockIdx.x * 256 + threadIdx.x) * 4;
    float4 v = *(const float4*)(hs + i);
    *(__half2*)(g_Xh + i)     = __halves2half2(__float2half_rn(v.x), __float2half_rn(v.y));
    *(__half2*)(g_Xh + i + 2) = __halves2half2(__float2half_rn(v.z), __float2half_rn(v.w));
}

__global__ __launch_bounds__(256) void wt_kernel(
    const float* __restrict__ qw, const float* __restrict__ kw,
    const float* __restrict__ vw, const float* __restrict__ ow)
{
    int w = blockIdx.z;
    const float* W = (w == 0) ? qw : (w == 1) ? kw : (w == 2) ? vw : ow;
    __half* WTh = g_Wh[w];
    __shared__ float t[32][33];
    int n0 = blockIdx.x * 32, k0 = blockIdx.y * 32;
    int tx = threadIdx.x & 31, ty = threadIdx.x >> 5;
#pragma unroll
    for (int i = 0; i < 4; i++)
        t[ty + i * 8][tx] = W[(size_t)(k0 + ty + i * 8) * Hh + n0 + tx];
    __syncthreads();
#pragma unroll
    for (int i = 0; i < 4; i++) {
        float x = t[tx][ty + i * 8];
        __half h, l;
        split_f(x, h, l);
        size_t idx = (size_t)(n0 + ty + i * 8) * Hh + k0 + tx;
        WTh[idx] = h;
        if (w == 3) g_Wl[idx] = l;
    }
}

// ---------------------------------------------------------------------------
// Per-(b,s) gating (1/sqrt(HD) folded)
// ---------------------------------------------------------------------------
__global__ __launch_bounds__(256) void gate_kernel(
    const float* __restrict__ hs, const float* __restrict__ pros,
    const float* __restrict__ pg_w, const float* __restrict__ pg_b,
    const float* __restrict__ mg_w, const float* __restrict__ mg_b)
{
    int bs = blockIdx.x;
    const float* x = hs + (size_t)bs * Hh;
    int tid = threadIdx.x, lane = tid & 31, wrp = tid >> 5;

    float part = 0.f;
    for (int i = tid; i < Hh; i += 256) part += x[i] * mg_w[i];
#pragma unroll
    for (int o = 16; o; o >>= 1) part += __shfl_xor_sync(0xffffffffu, part, o);
    __shared__ float red[8];
    if (lane == 0) red[wrp] = part;
    __syncthreads();
    float tot = 0.f;
#pragma unroll
    for (int w = 0; w < 8; w++) tot += red[w];
    float mem = 1.0f + 0.5f / (1.0f + __expf(-(tot + mg_b[0])));

    if (tid < NHh) {
        const float* p = pros + (size_t)bs * 4;
        float a = p[0] * pg_w[0 * NHh + tid] + p[1] * pg_w[1 * NHh + tid]
                + p[2] * pg_w[2 * NHh + tid] + p[3] * pg_w[3 * NHh + tid]
                + pg_b[tid];
        float pg = 1.0f + 1.0f / (1.0f + __expf(-a));
        g_gain[(size_t)bs * NHh + tid] = pg * mem * 0.125f;
    }
}

// ---------------------------------------------------------------------------
extern "C" void kernel_launch(void* const* d_in, const int* in_sizes, int n_in,
                              void* d_out, int out_size)
{
    const float* hs   = (const float*)d_in[0];
    const float* pros = (const float*)d_in[1];
    const float* q_w  = (const float*)d_in[2];
    const float* q_b  = (const float*)d_in[3];
    const float* k_w  = (const float*)d_in[4];
    const float* k_b  = (const float*)d_in[5];
    const float* v_w  = (const float*)d_in[6];
    const float* v_b  = (const float*)d_in[7];
    const float* o_w  = (const float*)d_in[8];
    const float* o_b  = (const float*)d_in[9];
    const float* pg_w = (const float*)d_in[10];
    const float* pg_b = (const float*)d_in[11];
    const float* mg_w = (const float*)d_in[12];
    const float* mg_b = (const float*)d_in[13];

    float* out  = (float*)d_out;
    float* attn = out + (size_t)Bb * Ss * Hh;

    static int attr_done = 0;
    if (!attr_done) {
        cudaFuncSetAttribute(gemm_qkv,   cudaFuncAttributeMaxDynamicSharedMemorySize, SMEM_QKV);
        cudaFuncSetAttribute(gemm_out,   cudaFuncAttributeMaxDynamicSharedMemorySize, SMEM_OUT);
        cudaFuncSetAttribute(scores_mma, cudaFuncAttributeMaxDynamicSharedMemorySize, SMEM_SC);
        cudaFuncSetAttribute(pv_mma,     cudaFuncAttributeMaxDynamicSharedMemorySize, SMEM_PV);
        attr_done = 1;
    }

    gate_kernel<<<Bb * Ss, 256>>>(hs, pros, pg_w, pg_b, mg_w, mg_b);
    x_conv<<<(Mtot * Hh) / (256 * 4), 256>>>(hs);
    wt_kernel<<<dim3(32, 32, 4), 256>>>(q_w, k_w, v_w, o_w);

    gemm_qkv<<<dim3(8, 32, 3), 256, SMEM_QKV>>>(q_b, k_b, v_b);
    vt_kernel<<<dim3(64, 2, 32), 256>>>();

    scores_mma<<<dim3(16, 16, 32), 256, SMEM_SC>>>(attn);
    softmax_kernel<<<dim3(Ss / 2, NHh, Bb), 256>>>(attn);
    pv_mma<<<dim3(16, 32), 256, SMEM_PV>>>();

    gemm_out<<<dim3(8, 32), 256, SMEM_OUT>>>(o_b, out);
}

// round 15
// speedup vs baseline: 1.0345x; 1.0345x over previous
#include <cuda_runtime.h>
#include <cuda_fp16.h>
#include <math.h>
#include <stdint.h>

#define Bb  2
#define Ss  2048
#define Hh  1024
#define NHh 16
#define HDd 64
#define Mtot (Bb * Ss)          // 4096

// ---------------- scratch planes (__device__ globals; no allocs) -----------
__device__ __half g_Xh[(size_t)Mtot * Hh];            // fp16-rounded X
__device__ __half g_Wh[4][(size_t)Hh * Hh];           // transposed weights hi
__device__ __half g_Wl[(size_t)Hh * Hh];              // o_w lo plane only
__device__ __half g_Qh[(size_t)Bb * NHh * Ss * HDd];  // Q hi (gain folded)
__device__ __half g_Kh[(size_t)Bb * NHh * Ss * HDd];
__device__ __half g_Vh[(size_t)Bb * NHh * Ss * HDd];  // V fp16 (pre-rounded)
__device__ __half g_VTh[(size_t)Bb * NHh * HDd * Ss];
__device__ __half g_Ph[(size_t)Bb * NHh * Ss * Ss];   // prob hi plane (pad stays 0)
__device__ __half g_Ch[(size_t)Mtot * Hh];            // fp16 ctx
__device__ float  g_gain[(size_t)Bb * Ss * NHh];

// ---------------- helpers ---------------------------------------------------
__device__ __forceinline__ uint32_t smem_u32(const void* p) {
    uint32_t a;
    asm("{ .reg .u64 t; cvta.to.shared.u64 t, %1; cvt.u32.u64 %0, t; }" : "=r"(a) : "l"(p));
    return a;
}
__device__ __forceinline__ void split_f(float x, __half& h, __half& l) {
    h = __float2half_rn(x);
    l = __float2half_rn(x - __half2float(h));
}
__device__ __forceinline__ void ldsm4(uint32_t* r, uint32_t addr) {
    asm volatile("ldmatrix.sync.aligned.m8n8.x4.shared.b16 {%0,%1,%2,%3}, [%4];"
        : "=r"(r[0]), "=r"(r[1]), "=r"(r[2]), "=r"(r[3]) : "r"(addr));
}
__device__ __forceinline__ void mma16(float* c, const uint32_t* a, const uint32_t* b) {
    asm volatile("mma.sync.aligned.m16n8k16.row.col.f32.f16.f16.f32 "
        "{%0,%1,%2,%3},{%4,%5,%6,%7},{%8,%9},{%0,%1,%2,%3};"
        : "+f"(c[0]), "+f"(c[1]), "+f"(c[2]), "+f"(c[3])
        : "r"(a[0]), "r"(a[1]), "r"(a[2]), "r"(a[3]), "r"(b[0]), "r"(b[1]));
}
__device__ __forceinline__ void cpa16(uint32_t dst, const void* src) {
    asm volatile("cp.async.cg.shared.global [%0], [%1], 16;" :: "r"(dst), "l"(src));
}
template<int N>
__device__ __forceinline__ void cp_wait() {
    asm volatile("cp.async.wait_group %0;" :: "n"(N < 0 ? 0 : N));
}

// ---------------------------------------------------------------------------
// Split-fp16 tensor-core mainloop (R12 form, BK=64).
// AP/BP = #planes A/B. NS = pipeline stages, ONE __syncthreads per k-chunk.
// C[128 x BN] += A[128 x 64*nkc] @ Bt[BN x 64*nkc]^T, K-major planes.
// 8 warps: 4 M x 2 N; warp tile = 32 x (BN/2).
// ---------------------------------------------------------------------------
template<int BN, int AP, int BP, int NS>
__device__ __forceinline__ void split_mainloop(
    const __half* __restrict__ Ah, const __half* __restrict__ Al, int ldA,
    const __half* __restrict__ Bh, const __half* __restrict__ Bl, int ldB,
    int nkc, char* smem, float (*cacc)[4])
{
    constexpr int NT = BN / 16;
    constexpr int APL = 128 * 128;       // bytes per A plane
    constexpr int BPL = BN * 128;        // bytes per B plane
    constexpr int BUF = AP * APL + BP * BPL;

    const int tid = threadIdx.x, lane = tid & 31, wid = tid >> 5;
    const int m_base = (wid & 3) * 32;
    const int n_base = (wid >> 2) * (BN / 2);
    uint32_t sbase = smem_u32(smem);

    auto load = [&](int kc, int b) {
        uint32_t s0 = sbase + b * BUF;
        for (int idx = tid; idx < 1024; idx += 256) {
            int row = idx >> 3, ch = idx & 7;
            uint32_t off = row * 128 + ((ch ^ (row & 7)) << 4);
            cpa16(s0 + off, Ah + (size_t)row * ldA + kc * 64 + ch * 8);
            if (AP == 2)
                cpa16(s0 + APL + off, Al + (size_t)row * ldA + kc * 64 + ch * 8);
        }
        for (int idx = tid; idx < BN * 8; idx += 256) {
            int row = idx >> 3, ch = idx & 7;
            uint32_t off = row * 128 + ((ch ^ (row & 7)) << 4);
            cpa16(s0 + AP * APL + off, Bh + (size_t)row * ldB + kc * 64 + ch * 8);
            if (BP == 2)
                cpa16(s0 + AP * APL + BPL + off, Bl + (size_t)row * ldB + kc * 64 + ch * 8);
        }
        asm volatile("cp.async.commit_group;");
    };

#pragma unroll
    for (int s = 0; s < NS - 1; s++)
        if (s < nkc) load(s, s);

    for (int kc = 0; kc < nkc; kc++) {
        int b = kc % NS;
        if (kc + NS - 1 < nkc) cp_wait<NS - 2>();
        else                   cp_wait<0>();
        __syncthreads();
        if (kc + NS - 1 < nkc) load(kc + NS - 1, (kc + NS - 1) % NS);
        uint32_t s0 = sbase + b * BUF;
#pragma unroll
        for (int ks = 0; ks < 4; ks++) {
            uint32_t a[AP][2][4];
            {
                int row = m_base + (lane & 7) + ((lane >> 3) & 1) * 8;
                int ch  = ks * 2 + (lane >> 4);
#pragma unroll
                for (int mt = 0; mt < 2; mt++) {
                    int r2 = row + mt * 16;
                    uint32_t off = r2 * 128 + ((ch ^ (r2 & 7)) << 4);
                    ldsm4(a[0][mt], s0 + off);
                    if (AP == 2) ldsm4(a[1][mt], s0 + APL + off);
                }
            }
            uint32_t bf[BP][NT][2];
            {
                int row = n_base + (lane & 7) + ((lane >> 4) << 3);
                int ch  = ks * 2 + ((lane >> 3) & 1);
#pragma unroll
                for (int np = 0; np < NT / 2; np++) {
                    int r2 = row + np * 16;
                    uint32_t off = r2 * 128 + ((ch ^ (r2 & 7)) << 4);
                    uint32_t t[4];
                    ldsm4(t, s0 + AP * APL + off);
                    bf[0][2 * np][0] = t[0]; bf[0][2 * np][1] = t[1];
                    bf[0][2 * np + 1][0] = t[2]; bf[0][2 * np + 1][1] = t[3];
                    if (BP == 2) {
                        ldsm4(t, s0 + AP * APL + BPL + off);
                        bf[1][2 * np][0] = t[0]; bf[1][2 * np][1] = t[1];
                        bf[1][2 * np + 1][0] = t[2]; bf[1][2 * np + 1][1] = t[3];
                    }
                }
            }
#pragma unroll
            for (int mt = 0; mt < 2; mt++)
#pragma unroll
                for (int nt = 0; nt < NT; nt++) {
                    float* c = cacc[mt * NT + nt];
                    mma16(c, a[0][mt], bf[0][nt]);
                    if (BP == 2) mma16(c, a[0][mt], bf[1][nt]);
                    if (AP == 2) mma16(c, a[1][mt], bf[0][nt]);
                }
        }
    }
}

#define BUF_N128_B1 (128 * 128 + 128 * 128)       // 32 KB
#define BUF_N128_B2 (128 * 128 + 2 * 128 * 128)   // 48 KB
#define BUF_N64_B1  (128 * 128 + 64 * 128)        // 24 KB
#define SMEM_QKV (3 * BUF_N128_B1)                // 96 KB
#define SMEM_OUT (2 * BUF_N128_B2)                // 96 KB
#define SMEM_SC  (BUF_N128_B1)                    // 32 KB (nkc=1)
#define SMEM_PV  (3 * BUF_N64_B1)                 // 72 KB

// ---------------------------------------------------------------------------
// QKV projection (z selects Q/K/V). BM=128, BN=128 (two heads per block).
// Plain fp16 GEMM. Q gain folded; V emits fp16 (same rounding as R12's vt).
// ---------------------------------------------------------------------------
__global__ __launch_bounds__(256, 2) void gemm_qkv(
    const float* __restrict__ bq, const float* __restrict__ bk,
    const float* __restrict__ bv)
{
    extern __shared__ char smem[];
    const int z = blockIdx.z;
    const int n0 = blockIdx.x * 128, m0 = blockIdx.y * 128;
    const float* bias = (z == 0) ? bq : (z == 1) ? bk : bv;

    float c[16][4];
#pragma unroll
    for (int i = 0; i < 16; i++)
#pragma unroll
        for (int j = 0; j < 4; j++) c[i][j] = 0.f;

    split_mainloop<128, 1, 1, 3>(g_Xh + (size_t)m0 * Hh, nullptr, Hh,
                                 g_Wh[z] + (size_t)n0 * Hh, nullptr, Hh,
                                 16, smem, c);

    const int lane = threadIdx.x & 31, wid = threadIdx.x >> 5;
    const int g = lane >> 2, t = lane & 3;
    const int m_base = (wid & 3) * 32, n_base = (wid >> 2) * 64;
#pragma unroll
    for (int mt = 0; mt < 2; mt++)
#pragma unroll
        for (int nt = 0; nt < 8; nt++)
#pragma unroll
            for (int half = 0; half < 2; half++) {
                int m = m0 + m_base + mt * 16 + g + half * 8;
                int n = n0 + n_base + nt * 8 + 2 * t;
                float vx = c[mt * 8 + nt][half * 2 + 0] + bias[n];
                float vy = c[mt * 8 + nt][half * 2 + 1] + bias[n + 1];
                int h = n >> 6, d = n & 63;
                int bidx = m >> 11, srow = m & (Ss - 1);
                size_t base = (((size_t)(bidx * NHh + h)) * Ss + srow) * HDd + d;
                if (z == 0) {
                    float gs = g_gain[(size_t)m * NHh + h];
                    vx *= gs; vy *= gs;
                }
                __half2 hv = __halves2half2(__float2half_rn(vx), __float2half_rn(vy));
                __half* dst = (z == 0) ? g_Qh : (z == 1) ? g_Kh : g_Vh;
                *(__half2*)(dst + base) = hv;
            }
}

// ---------------------------------------------------------------------------
// Output projection: fp16 ctx @ o_w + o_b -> d_out[:B*S*H] (fp32). 2 MMAs.
// ---------------------------------------------------------------------------
__global__ __launch_bounds__(256, 2) void gemm_out(
    const float* __restrict__ bias, float* __restrict__ out)
{
    extern __shared__ char smem[];
    const int n0 = blockIdx.x * 128, m0 = blockIdx.y * 128;

    float c[16][4];
#pragma unroll
    for (int i = 0; i < 16; i++)
#pragma unroll
        for (int j = 0; j < 4; j++) c[i][j] = 0.f;

    split_mainloop<128, 1, 2, 2>(g_Ch + (size_t)m0 * Hh, nullptr, Hh,
                                 g_Wh[3] + (size_t)n0 * Hh, g_Wl + (size_t)n0 * Hh, Hh,
                                 16, smem, c);

    const int lane = threadIdx.x & 31, wid = threadIdx.x >> 5;
    const int g = lane >> 2, t = lane & 3;
    const int m_base = (wid & 3) * 32, n_base = (wid >> 2) * 64;
#pragma unroll
    for (int mt = 0; mt < 2; mt++)
#pragma unroll
        for (int nt = 0; nt < 8; nt++)
#pragma unroll
            for (int half = 0; half < 2; half++) {
                int m = m0 + m_base + mt * 16 + g + half * 8;
                int n = n0 + n_base + nt * 8 + 2 * t;
                float2 v = make_float2(c[mt * 8 + nt][half * 2] + bias[n],
                                       c[mt * 8 + nt][half * 2 + 1] + bias[n + 1]);
                *(float2*)(out + (size_t)m * Hh + n) = v;
            }
}

// ---------------------------------------------------------------------------
// Scores: 128 q-rows x 128 k-cols per block; 1-MMA (Qh*Kh).
// ---------------------------------------------------------------------------
__global__ __launch_bounds__(256, 2) void scores_mma(float* __restrict__ attn)
{
    extern __shared__ char smem[];
    const int kt = blockIdx.x, qt = blockIdx.y, bh = blockIdx.z;
    const int q0 = qt * 128, k0 = kt * 128;
    float* abase = attn + (size_t)bh * Ss * Ss;

    if (kt > qt) {
        float4 z4 = make_float4(0.f, 0.f, 0.f, 0.f);
        for (int idx = threadIdx.x; idx < 128 * 32; idx += 256) {
            int row = idx >> 5, cc = idx & 31;
            *(float4*)(abase + (size_t)(q0 + row) * Ss + k0 + cc * 4) = z4;
        }
        return;
    }

    float c[16][4];
#pragma unroll
    for (int i = 0; i < 16; i++)
#pragma unroll
        for (int j = 0; j < 4; j++) c[i][j] = 0.f;

    size_t qoff = ((size_t)bh * Ss + q0) * HDd;
    size_t koff = ((size_t)bh * Ss + k0) * HDd;
    split_mainloop<128, 1, 1, 2>(g_Qh + qoff, nullptr, HDd,
                                 g_Kh + koff, nullptr, HDd, 1, smem, c);

    const int lane = threadIdx.x & 31, wid = threadIdx.x >> 5;
    const int g = lane >> 2, t = lane & 3;
    const int m_base = (wid & 3) * 32, n_base = (wid >> 2) * 64;
    const bool diag = (kt == qt);
#pragma unroll
    for (int mt = 0; mt < 2; mt++)
#pragma unroll
        for (int nt = 0; nt < 8; nt++)
#pragma unroll
            for (int half = 0; half < 2; half++) {
                int gi = q0 + m_base + mt * 16 + g + half * 8;
                int gj = k0 + n_base + nt * 8 + 2 * t;
                float vx = c[mt * 8 + nt][half * 2];
                float vy = c[mt * 8 + nt][half * 2 + 1];
                if (diag) {
                    if (gj > gi) vx = 0.f;
                    if (gj + 1 > gi) vy = 0.f;
                }
                *(float2*)(abase + (size_t)gi * Ss + gj) = make_float2(vx, vy);
            }
}

// ---------------------------------------------------------------------------
// Softmax over j<=i (R12 version: one row per 256-thread block).
// float4 loads/stores, shfl warp reductions, 2 barriers.
// Writes fp32 weights (d_out) + fp16 prob plane.
// ---------------------------------------------------------------------------
__global__ __launch_bounds__(256) void softmax_kernel(float* __restrict__ attn)
{
    int i = blockIdx.x, h = blockIdx.y, b = blockIdx.z;
    size_t roff = ((size_t)(b * NHh + h) * Ss + i) * Ss;
    float* row = attn + roff;
    __half* prh = g_Ph + roff;
    const int n = i + 1;
    const int n4 = n & ~3;
    const int tail = n - n4;
    const int tid = threadIdx.x, lane = tid & 31, wrp = tid >> 5;

    float vals[9];
    int cnt = 0;
    float mx = -INFINITY;
    for (int j = tid * 4; j < n4; j += 1024) {
        float4 v = *(const float4*)(row + j);
        vals[cnt++] = v.x; vals[cnt++] = v.y; vals[cnt++] = v.z; vals[cnt++] = v.w;
        mx = fmaxf(mx, fmaxf(fmaxf(v.x, v.y), fmaxf(v.z, v.w)));
    }
    if (tid < tail) {
        float s = row[n4 + tid];
        vals[cnt++] = s;
        mx = fmaxf(mx, s);
    }

#pragma unroll
    for (int o = 16; o; o >>= 1) mx = fmaxf(mx, __shfl_xor_sync(0xffffffffu, mx, o));
    __shared__ float rmax[8], rsum[8];
    if (lane == 0) rmax[wrp] = mx;
    __syncthreads();
    mx = rmax[0];
#pragma unroll
    for (int w = 1; w < 8; w++) mx = fmaxf(mx, rmax[w]);

    float sum = 0.f;
    for (int c2 = 0; c2 < cnt; c2++) {
        vals[c2] = __expf(vals[c2] - mx);
        sum += vals[c2];
    }
#pragma unroll
    for (int o = 16; o; o >>= 1) sum += __shfl_xor_sync(0xffffffffu, sum, o);
    if (lane == 0) rsum[wrp] = sum;
    __syncthreads();
    sum = 0.f;
#pragma unroll
    for (int w = 0; w < 8; w++) sum += rsum[w];
    float inv = 1.0f / sum;

    cnt = 0;
    for (int j = tid * 4; j < n4; j += 1024) {
        float4 v;
        v.x = vals[cnt++] * inv; v.y = vals[cnt++] * inv;
        v.z = vals[cnt++] * inv; v.w = vals[cnt++] * inv;
        *(float4*)(row + j) = v;
        *(__half2*)(prh + j)     = __halves2half2(__float2half_rn(v.x), __float2half_rn(v.y));
        *(__half2*)(prh + j + 2) = __halves2half2(__float2half_rn(v.z), __float2half_rn(v.w));
    }
    if (tid < tail) {
        float p = vals[cnt++] * inv;
        row[n4 + tid] = p;
        prh[n4 + tid] = __float2half_rn(p);
    }
}

// ---------------------------------------------------------------------------
// V transpose: g_Vh[bh][s][d] -> VTh[bh][d][s] (fp16 in/out)
// ---------------------------------------------------------------------------
__global__ __launch_bounds__(256) void vt_kernel()
{
    int bh = blockIdx.z;
    const __half* V = g_Vh + (size_t)bh * Ss * HDd;
    __half* VTh = g_VTh + (size_t)bh * HDd * Ss;
    __shared__ __half t[32][33];
    int s0 = blockIdx.x * 32, d0 = blockIdx.y * 32;
    int tx = threadIdx.x & 31, ty = threadIdx.x >> 5;
#pragma unroll
    for (int i = 0; i < 4; i++)
        t[ty + i * 8][tx] = V[(size_t)(s0 + ty + i * 8) * HDd + d0 + tx];
    __syncthreads();
#pragma unroll
    for (int i = 0; i < 4; i++)
        VTh[(size_t)(d0 + ty + i * 8) * Ss + s0 + tx] = t[tx][ty + i * 8];
}

// ---------------------------------------------------------------------------
// PV: ctx = probs @ V (causal). Single-plane both sides, BK=64, NS=3 (R12).
// ---------------------------------------------------------------------------
__global__ __launch_bounds__(256, 2) void pv_mma()
{
    extern __shared__ char smem[];
    const int qt = blockIdx.x, bh = blockIdx.y;
    const int q0 = qt * 128;
    const int b = bh >> 4, h = bh & 15;

    float c[8][4];
#pragma unroll
    for (int i = 0; i < 8; i++)
#pragma unroll
        for (int j = 0; j < 4; j++) c[i][j] = 0.f;

    size_t poff = ((size_t)bh * Ss + q0) * Ss;
    size_t voff = (size_t)bh * HDd * Ss;
    split_mainloop<64, 1, 1, 3>(g_Ph + poff, nullptr, Ss,
                                g_VTh + voff, nullptr, Ss,
                                (qt + 1) * 2, smem, c);

    const int lane = threadIdx.x & 31, wid = threadIdx.x >> 5;
    const int g = lane >> 2, t = lane & 3;
    const int m_base = (wid & 3) * 32, n_base = (wid >> 2) * 32;
#pragma unroll
    for (int mt = 0; mt < 2; mt++)
#pragma unroll
        for (int nt = 0; nt < 4; nt++)
#pragma unroll
            for (int half = 0; half < 2; half++) {
                int m = q0 + m_base + mt * 16 + g + half * 8;
                int d = n_base + nt * 8 + 2 * t;
                __half hx = __float2half_rn(c[mt * 4 + nt][half * 2]);
                __half hy = __float2half_rn(c[mt * 4 + nt][half * 2 + 1]);
                size_t base = ((size_t)b * Ss + m) * Hh + h * 64 + d;
                *(__half2*)(g_Ch + base) = __halves2half2(hx, hy);
            }
}

// ---------------------------------------------------------------------------
// Prep: X fp16 plane; weight transpose (+ lo plane for o_w only).
// ---------------------------------------------------------------------------
__global__ __launch_bounds__(256) void x_conv(const float* __restrict__ hs)
{
    size_t i = ((size_t)blockIdx.x * 256 + threadIdx.x) * 4;
    float4 v = *(const float4*)(hs + i);
    *(__half2*)(g_Xh + i)     = __halves2half2(__float2half_rn(v.x), __float2half_rn(v.y));
    *(__half2*)(g_Xh + i + 2) = __halves2half2(__float2half_rn(v.z), __float2half_rn(v.w));
}

__global__ __launch_bounds__(256) void wt_kernel(
    const float* __restrict__ qw, const float* __restrict__ kw,
    const float* __restrict__ vw, const float* __restrict__ ow)
{
    int w = blockIdx.z;
    const float* W = (w == 0) ? qw : (w == 1) ? kw : (w == 2) ? vw : ow;
    __half* WTh = g_Wh[w];
    __shared__ float t[32][33];
    int n0 = blockIdx.x * 32, k0 = blockIdx.y * 32;
    int tx = threadIdx.x & 31, ty = threadIdx.x >> 5;
#pragma unroll
    for (int i = 0; i < 4; i++)
        t[ty + i * 8][tx] = W[(size_t)(k0 + ty + i * 8) * Hh + n0 + tx];
    __syncthreads();
#pragma unroll
    for (int i = 0; i < 4; i++) {
        float x = t[tx][ty + i * 8];
        __half h, l;
        split_f(x, h, l);
        size_t idx = (size_t)(n0 + ty + i * 8) * Hh + k0 + tx;
        WTh[idx] = h;
        if (w == 3) g_Wl[idx] = l;
    }
}

// ---------------------------------------------------------------------------
// Per-(b,s) gating (1/sqrt(HD) folded)
// ---------------------------------------------------------------------------
__global__ __launch_bounds__(256) void gate_kernel(
    const float* __restrict__ hs, const float* __restrict__ pros,
    const float* __restrict__ pg_w, const float* __restrict__ pg_b,
    const float* __restrict__ mg_w, const float* __restrict__ mg_b)
{
    int bs = blockIdx.x;
    const float* x = hs + (size_t)bs * Hh;
    int tid = threadIdx.x, lane = tid & 31, wrp = tid >> 5;

    float part = 0.f;
    for (int i = tid; i < Hh; i += 256) part += x[i] * mg_w[i];
#pragma unroll
    for (int o = 16; o; o >>= 1) part += __shfl_xor_sync(0xffffffffu, part, o);
    __shared__ float red[8];
    if (lane == 0) red[wrp] = part;
    __syncthreads();
    float tot = 0.f;
#pragma unroll
    for (int w = 0; w < 8; w++) tot += red[w];
    float mem = 1.0f + 0.5f / (1.0f + __expf(-(tot + mg_b[0])));

    if (tid < NHh) {
        const float* p = pros + (size_t)bs * 4;
        float a = p[0] * pg_w[0 * NHh + tid] + p[1] * pg_w[1 * NHh + tid]
                + p[2] * pg_w[2 * NHh + tid] + p[3] * pg_w[3 * NHh + tid]
                + pg_b[tid];
        float pg = 1.0f + 1.0f / (1.0f + __expf(-a));
        g_gain[(size_t)bs * NHh + tid] = pg * mem * 0.125f;
    }
}

// ---------------------------------------------------------------------------
extern "C" void kernel_launch(void* const* d_in, const int* in_sizes, int n_in,
                              void* d_out, int out_size)
{
    const float* hs   = (const float*)d_in[0];
    const float* pros = (const float*)d_in[1];
    const float* q_w  = (const float*)d_in[2];
    const float* q_b  = (const float*)d_in[3];
    const float* k_w  = (const float*)d_in[4];
    const float* k_b  = (const float*)d_in[5];
    const float* v_w  = (const float*)d_in[6];
    const float* v_b  = (const float*)d_in[7];
    const float* o_w  = (const float*)d_in[8];
    const float* o_b  = (const float*)d_in[9];
    const float* pg_w = (const float*)d_in[10];
    const float* pg_b = (const float*)d_in[11];
    const float* mg_w = (const float*)d_in[12];
    const float* mg_b = (const float*)d_in[13];

    float* out  = (float*)d_out;
    float* attn = out + (size_t)Bb * Ss * Hh;

    static int attr_done = 0;
    if (!attr_done) {
        cudaFuncSetAttribute(gemm_qkv,   cudaFuncAttributeMaxDynamicSharedMemorySize, SMEM_QKV);
        cudaFuncSetAttribute(gemm_out,   cudaFuncAttributeMaxDynamicSharedMemorySize, SMEM_OUT);
        cudaFuncSetAttribute(scores_mma, cudaFuncAttributeMaxDynamicSharedMemorySize, SMEM_SC);
        cudaFuncSetAttribute(pv_mma,     cudaFuncAttributeMaxDynamicSharedMemorySize, SMEM_PV);
        attr_done = 1;
    }

    gate_kernel<<<Bb * Ss, 256>>>(hs, pros, pg_w, pg_b, mg_w, mg_b);
    x_conv<<<(Mtot * Hh) / (256 * 4), 256>>>(hs);
    wt_kernel<<<dim3(32, 32, 4), 256>>>(q_w, k_w, v_w, o_w);

    gemm_qkv<<<dim3(8, 32, 3), 256, SMEM_QKV>>>(q_b, k_b, v_b);
    vt_kernel<<<dim3(64, 2, 32), 256>>>();

    scores_mma<<<dim3(16, 16, 32), 256, SMEM_SC>>>(attn);
    softmax_kernel<<<dim3(Ss, NHh, Bb), 256>>>(attn);
    pv_mma<<<dim3(16, 32), 256, SMEM_PV>>>();

    gemm_out<<<dim3(8, 32), 256, SMEM_OUT>>>(o_b, out);
}

// round 16
// speedup vs baseline: 1.0422x; 1.0074x over previous
#include <cuda_runtime.h>
#include <cuda_fp16.h>
#include <math.h>
#include <stdint.h>

#define Bb  2
#define Ss  2048
#define Hh  1024
#define NHh 16
#define HDd 64
#define Mtot (Bb * Ss)          // 4096

// ---------------- scratch planes (__device__ globals; no allocs) -----------
__device__ __half g_Xh[(size_t)Mtot * Hh];            // fp16-rounded X
__device__ __half g_Wh[4][(size_t)Hh * Hh];           // transposed weights hi
__device__ __half g_Wl[(size_t)Hh * Hh];              // o_w lo plane only
__device__ __half g_Qh[(size_t)Bb * NHh * Ss * HDd];  // Q hi (gain folded)
__device__ __half g_Kh[(size_t)Bb * NHh * Ss * HDd];
__device__ __half g_Vh[(size_t)Bb * NHh * Ss * HDd];  // V fp16 (pre-rounded)
__device__ __half g_VTh[(size_t)Bb * NHh * HDd * Ss];
__device__ __half g_Ph[(size_t)Bb * NHh * Ss * Ss];   // prob hi plane (pad stays 0)
__device__ __half g_Ch[(size_t)Mtot * Hh];            // fp16 ctx
__device__ float  g_gain[(size_t)Bb * Ss * NHh];

// ---------------- helpers ---------------------------------------------------
__device__ __forceinline__ uint32_t smem_u32(const void* p) {
    uint32_t a;
    asm("{ .reg .u64 t; cvta.to.shared.u64 t, %1; cvt.u32.u64 %0, t; }" : "=r"(a) : "l"(p));
    return a;
}
__device__ __forceinline__ void split_f(float x, __half& h, __half& l) {
    h = __float2half_rn(x);
    l = __float2half_rn(x - __half2float(h));
}
__device__ __forceinline__ void ldsm4(uint32_t* r, uint32_t addr) {
    asm volatile("ldmatrix.sync.aligned.m8n8.x4.shared.b16 {%0,%1,%2,%3}, [%4];"
        : "=r"(r[0]), "=r"(r[1]), "=r"(r[2]), "=r"(r[3]) : "r"(addr));
}
__device__ __forceinline__ void mma16(float* c, const uint32_t* a, const uint32_t* b) {
    asm volatile("mma.sync.aligned.m16n8k16.row.col.f32.f16.f16.f32 "
        "{%0,%1,%2,%3},{%4,%5,%6,%7},{%8,%9},{%0,%1,%2,%3};"
        : "+f"(c[0]), "+f"(c[1]), "+f"(c[2]), "+f"(c[3])
        : "r"(a[0]), "r"(a[1]), "r"(a[2]), "r"(a[3]), "r"(b[0]), "r"(b[1]));
}
__device__ __forceinline__ void cpa16(uint32_t dst, const void* src) {
    asm volatile("cp.async.cg.shared.global [%0], [%1], 16;" :: "r"(dst), "l"(src));
}
template<int N>
__device__ __forceinline__ void cp_wait() {
    asm volatile("cp.async.wait_group %0;" :: "n"(N < 0 ? 0 : N));
}

// ---------------------------------------------------------------------------
// Split-fp16 tensor-core mainloop (BK=64).
// AP/BP = #planes A/B. NS = pipeline stages, ONE __syncthreads per k-chunk.
// C[128 x BN] += A[128 x 64*nkc] @ Bt[BN x 64*nkc]^T, K-major planes.
// 8 warps: 4 M x 2 N; warp tile = 32 x (BN/2).
// ---------------------------------------------------------------------------
template<int BN, int AP, int BP, int NS>
__device__ __forceinline__ void split_mainloop(
    const __half* __restrict__ Ah, const __half* __restrict__ Al, int ldA,
    const __half* __restrict__ Bh, const __half* __restrict__ Bl, int ldB,
    int nkc, char* smem, float (*cacc)[4])
{
    constexpr int NT = BN / 16;
    constexpr int APL = 128 * 128;       // bytes per A plane
    constexpr int BPL = BN * 128;        // bytes per B plane
    constexpr int BUF = AP * APL + BP * BPL;

    const int tid = threadIdx.x, lane = tid & 31, wid = tid >> 5;
    const int m_base = (wid & 3) * 32;
    const int n_base = (wid >> 2) * (BN / 2);
    uint32_t sbase = smem_u32(smem);

    auto load = [&](int kc, int b) {
        uint32_t s0 = sbase + b * BUF;
        for (int idx = tid; idx < 1024; idx += 256) {
            int row = idx >> 3, ch = idx & 7;
            uint32_t off = row * 128 + ((ch ^ (row & 7)) << 4);
            cpa16(s0 + off, Ah + (size_t)row * ldA + kc * 64 + ch * 8);
            if (AP == 2)
                cpa16(s0 + APL + off, Al + (size_t)row * ldA + kc * 64 + ch * 8);
        }
        for (int idx = tid; idx < BN * 8; idx += 256) {
            int row = idx >> 3, ch = idx & 7;
            uint32_t off = row * 128 + ((ch ^ (row & 7)) << 4);
            cpa16(s0 + AP * APL + off, Bh + (size_t)row * ldB + kc * 64 + ch * 8);
            if (BP == 2)
                cpa16(s0 + AP * APL + BPL + off, Bl + (size_t)row * ldB + kc * 64 + ch * 8);
        }
        asm volatile("cp.async.commit_group;");
    };

#pragma unroll
    for (int s = 0; s < NS - 1; s++)
        if (s < nkc) load(s, s);

    for (int kc = 0; kc < nkc; kc++) {
        int b = kc % NS;
        if (kc + NS - 1 < nkc) cp_wait<NS - 2>();
        else                   cp_wait<0>();
        __syncthreads();
        if (kc + NS - 1 < nkc) load(kc + NS - 1, (kc + NS - 1) % NS);
        uint32_t s0 = sbase + b * BUF;
#pragma unroll
        for (int ks = 0; ks < 4; ks++) {
            uint32_t a[AP][2][4];
            {
                int row = m_base + (lane & 7) + ((lane >> 3) & 1) * 8;
                int ch  = ks * 2 + (lane >> 4);
#pragma unroll
                for (int mt = 0; mt < 2; mt++) {
                    int r2 = row + mt * 16;
                    uint32_t off = r2 * 128 + ((ch ^ (r2 & 7)) << 4);
                    ldsm4(a[0][mt], s0 + off);
                    if (AP == 2) ldsm4(a[1][mt], s0 + APL + off);
                }
            }
            uint32_t bf[BP][NT][2];
            {
                int row = n_base + (lane & 7) + ((lane >> 4) << 3);
                int ch  = ks * 2 + ((lane >> 3) & 1);
#pragma unroll
                for (int np = 0; np < NT / 2; np++) {
                    int r2 = row + np * 16;
                    uint32_t off = r2 * 128 + ((ch ^ (r2 & 7)) << 4);
                    uint32_t t[4];
                    ldsm4(t, s0 + AP * APL + off);
                    bf[0][2 * np][0] = t[0]; bf[0][2 * np][1] = t[1];
                    bf[0][2 * np + 1][0] = t[2]; bf[0][2 * np + 1][1] = t[3];
                    if (BP == 2) {
                        ldsm4(t, s0 + AP * APL + BPL + off);
                        bf[1][2 * np][0] = t[0]; bf[1][2 * np][1] = t[1];
                        bf[1][2 * np + 1][0] = t[2]; bf[1][2 * np + 1][1] = t[3];
                    }
                }
            }
#pragma unroll
            for (int mt = 0; mt < 2; mt++)
#pragma unroll
                for (int nt = 0; nt < NT; nt++) {
                    float* c = cacc[mt * NT + nt];
                    mma16(c, a[0][mt], bf[0][nt]);
                    if (BP == 2) mma16(c, a[0][mt], bf[1][nt]);
                    if (AP == 2) mma16(c, a[1][mt], bf[0][nt]);
                }
        }
    }
}

#define BUF_N128_B1 (128 * 128 + 128 * 128)       // 32 KB
#define BUF_N128_B2 (128 * 128 + 2 * 128 * 128)   // 48 KB
#define BUF_N64_B1  (128 * 128 + 64 * 128)        // 24 KB
#define SMEM_QKV (3 * BUF_N128_B1)                // 96 KB
#define SMEM_OUT (2 * BUF_N128_B2)                // 96 KB
#define SMEM_SC  (BUF_N128_B1)                    // 32 KB (nkc=1)
#define SMEM_PV  (3 * BUF_N64_B1)                 // 72 KB

// ---------------------------------------------------------------------------
// QKV projection (z selects Q/K/V). BM=128, BN=128 (two heads per block).
// ---------------------------------------------------------------------------
__global__ __launch_bounds__(256, 2) void gemm_qkv(
    const float* __restrict__ bq, const float* __restrict__ bk,
    const float* __restrict__ bv)
{
    extern __shared__ char smem[];
    const int z = blockIdx.z;
    const int n0 = blockIdx.x * 128, m0 = blockIdx.y * 128;
    const float* bias = (z == 0) ? bq : (z == 1) ? bk : bv;

    float c[16][4];
#pragma unroll
    for (int i = 0; i < 16; i++)
#pragma unroll
        for (int j = 0; j < 4; j++) c[i][j] = 0.f;

    split_mainloop<128, 1, 1, 3>(g_Xh + (size_t)m0 * Hh, nullptr, Hh,
                                 g_Wh[z] + (size_t)n0 * Hh, nullptr, Hh,
                                 16, smem, c);

    const int lane = threadIdx.x & 31, wid = threadIdx.x >> 5;
    const int g = lane >> 2, t = lane & 3;
    const int m_base = (wid & 3) * 32, n_base = (wid >> 2) * 64;
#pragma unroll
    for (int mt = 0; mt < 2; mt++)
#pragma unroll
        for (int nt = 0; nt < 8; nt++)
#pragma unroll
            for (int half = 0; half < 2; half++) {
                int m = m0 + m_base + mt * 16 + g + half * 8;
                int n = n0 + n_base + nt * 8 + 2 * t;
                float vx = c[mt * 8 + nt][half * 2 + 0] + bias[n];
                float vy = c[mt * 8 + nt][half * 2 + 1] + bias[n + 1];
                int h = n >> 6, d = n & 63;
                int bidx = m >> 11, srow = m & (Ss - 1);
                size_t base = (((size_t)(bidx * NHh + h)) * Ss + srow) * HDd + d;
                if (z == 0) {
                    float gs = g_gain[(size_t)m * NHh + h];
                    vx *= gs; vy *= gs;
                }
                __half2 hv = __halves2half2(__float2half_rn(vx), __float2half_rn(vy));
                __half* dst = (z == 0) ? g_Qh : (z == 1) ? g_Kh : g_Vh;
                *(__half2*)(dst + base) = hv;
            }
}

// ---------------------------------------------------------------------------
// Output projection: fp16 ctx @ o_w + o_b -> d_out[:B*S*H] (fp32). 2 MMAs.
// ---------------------------------------------------------------------------
__global__ __launch_bounds__(256, 2) void gemm_out(
    const float* __restrict__ bias, float* __restrict__ out)
{
    extern __shared__ char smem[];
    const int n0 = blockIdx.x * 128, m0 = blockIdx.y * 128;

    float c[16][4];
#pragma unroll
    for (int i = 0; i < 16; i++)
#pragma unroll
        for (int j = 0; j < 4; j++) c[i][j] = 0.f;

    split_mainloop<128, 1, 2, 2>(g_Ch + (size_t)m0 * Hh, nullptr, Hh,
                                 g_Wh[3] + (size_t)n0 * Hh, g_Wl + (size_t)n0 * Hh, Hh,
                                 16, smem, c);

    const int lane = threadIdx.x & 31, wid = threadIdx.x >> 5;
    const int g = lane >> 2, t = lane & 3;
    const int m_base = (wid & 3) * 32, n_base = (wid >> 2) * 64;
#pragma unroll
    for (int mt = 0; mt < 2; mt++)
#pragma unroll
        for (int nt = 0; nt < 8; nt++)
#pragma unroll
            for (int half = 0; half < 2; half++) {
                int m = m0 + m_base + mt * 16 + g + half * 8;
                int n = n0 + n_base + nt * 8 + 2 * t;
                float2 v = make_float2(c[mt * 8 + nt][half * 2] + bias[n],
                                       c[mt * 8 + nt][half * 2 + 1] + bias[n + 1]);
                *(float2*)(out + (size_t)m * Hh + n) = v;
            }
}

// ---------------------------------------------------------------------------
// Scores: 128 q-rows x 128 k-cols per block; 1-MMA (Qh*Kh).
// ---------------------------------------------------------------------------
__global__ __launch_bounds__(256, 2) void scores_mma(float* __restrict__ attn)
{
    extern __shared__ char smem[];
    const int kt = blockIdx.x, qt = blockIdx.y, bh = blockIdx.z;
    const int q0 = qt * 128, k0 = kt * 128;
    float* abase = attn + (size_t)bh * Ss * Ss;

    if (kt > qt) {
        float4 z4 = make_float4(0.f, 0.f, 0.f, 0.f);
        for (int idx = threadIdx.x; idx < 128 * 32; idx += 256) {
            int row = idx >> 5, cc = idx & 31;
            *(float4*)(abase + (size_t)(q0 + row) * Ss + k0 + cc * 4) = z4;
        }
        return;
    }

    float c[16][4];
#pragma unroll
    for (int i = 0; i < 16; i++)
#pragma unroll
        for (int j = 0; j < 4; j++) c[i][j] = 0.f;

    size_t qoff = ((size_t)bh * Ss + q0) * HDd;
    size_t koff = ((size_t)bh * Ss + k0) * HDd;
    split_mainloop<128, 1, 1, 2>(g_Qh + qoff, nullptr, HDd,
                                 g_Kh + koff, nullptr, HDd, 1, smem, c);

    const int lane = threadIdx.x & 31, wid = threadIdx.x >> 5;
    const int g = lane >> 2, t = lane & 3;
    const int m_base = (wid & 3) * 32, n_base = (wid >> 2) * 64;
    const bool diag = (kt == qt);
#pragma unroll
    for (int mt = 0; mt < 2; mt++)
#pragma unroll
        for (int nt = 0; nt < 8; nt++)
#pragma unroll
            for (int half = 0; half < 2; half++) {
                int gi = q0 + m_base + mt * 16 + g + half * 8;
                int gj = k0 + n_base + nt * 8 + 2 * t;
                float vx = c[mt * 8 + nt][half * 2];
                float vy = c[mt * 8 + nt][half * 2 + 1];
                if (diag) {
                    if (gj > gi) vx = 0.f;
                    if (gj + 1 > gi) vy = 0.f;
                }
                *(float2*)(abase + (size_t)gi * Ss + gj) = make_float2(vx, vy);
            }
}

// ---------------------------------------------------------------------------
// Softmax over j<=i (one row per 256-thread block).
// ---------------------------------------------------------------------------
__global__ __launch_bounds__(256) void softmax_kernel(float* __restrict__ attn)
{
    int i = blockIdx.x, h = blockIdx.y, b = blockIdx.z;
    size_t roff = ((size_t)(b * NHh + h) * Ss + i) * Ss;
    float* row = attn + roff;
    __half* prh = g_Ph + roff;
    const int n = i + 1;
    const int n4 = n & ~3;
    const int tail = n - n4;
    const int tid = threadIdx.x, lane = tid & 31, wrp = tid >> 5;

    float vals[9];
    int cnt = 0;
    float mx = -INFINITY;
    for (int j = tid * 4; j < n4; j += 1024) {
        float4 v = *(const float4*)(row + j);
        vals[cnt++] = v.x; vals[cnt++] = v.y; vals[cnt++] = v.z; vals[cnt++] = v.w;
        mx = fmaxf(mx, fmaxf(fmaxf(v.x, v.y), fmaxf(v.z, v.w)));
    }
    if (tid < tail) {
        float s = row[n4 + tid];
        vals[cnt++] = s;
        mx = fmaxf(mx, s);
    }

#pragma unroll
    for (int o = 16; o; o >>= 1) mx = fmaxf(mx, __shfl_xor_sync(0xffffffffu, mx, o));
    __shared__ float rmax[8], rsum[8];
    if (lane == 0) rmax[wrp] = mx;
    __syncthreads();
    mx = rmax[0];
#pragma unroll
    for (int w = 1; w < 8; w++) mx = fmaxf(mx, rmax[w]);

    float sum = 0.f;
    for (int c2 = 0; c2 < cnt; c2++) {
        vals[c2] = __expf(vals[c2] - mx);
        sum += vals[c2];
    }
#pragma unroll
    for (int o = 16; o; o >>= 1) sum += __shfl_xor_sync(0xffffffffu, sum, o);
    if (lane == 0) rsum[wrp] = sum;
    __syncthreads();
    sum = 0.f;
#pragma unroll
    for (int w = 0; w < 8; w++) sum += rsum[w];
    float inv = 1.0f / sum;

    cnt = 0;
    for (int j = tid * 4; j < n4; j += 1024) {
        float4 v;
        v.x = vals[cnt++] * inv; v.y = vals[cnt++] * inv;
        v.z = vals[cnt++] * inv; v.w = vals[cnt++] * inv;
        *(float4*)(row + j) = v;
        *(__half2*)(prh + j)     = __halves2half2(__float2half_rn(v.x), __float2half_rn(v.y));
        *(__half2*)(prh + j + 2) = __halves2half2(__float2half_rn(v.z), __float2half_rn(v.w));
    }
    if (tid < tail) {
        float p = vals[cnt++] * inv;
        row[n4 + tid] = p;
        prh[n4 + tid] = __float2half_rn(p);
    }
}

// ---------------------------------------------------------------------------
// V transpose: g_Vh[bh][s][d] -> VTh[bh][d][s] (fp16 in/out)
// ---------------------------------------------------------------------------
__global__ __launch_bounds__(256) void vt_kernel()
{
    int bh = blockIdx.z;
    const __half* V = g_Vh + (size_t)bh * Ss * HDd;
    __half* VTh = g_VTh + (size_t)bh * HDd * Ss;
    __shared__ __half t[32][33];
    int s0 = blockIdx.x * 32, d0 = blockIdx.y * 32;
    int tx = threadIdx.x & 31, ty = threadIdx.x >> 5;
#pragma unroll
    for (int i = 0; i < 4; i++)
        t[ty + i * 8][tx] = V[(size_t)(s0 + ty + i * 8) * HDd + d0 + tx];
    __syncthreads();
#pragma unroll
    for (int i = 0; i < 4; i++)
        VTh[(size_t)(d0 + ty + i * 8) * Ss + s0 + tx] = t[tx][ty + i * 8];
}

// ---------------------------------------------------------------------------
// PV: ctx = probs @ V (causal). Single-plane both sides, BK=64, NS=3.
// ---------------------------------------------------------------------------
__global__ __launch_bounds__(256, 2) void pv_mma()
{
    extern __shared__ char smem[];
    const int qt = blockIdx.x, bh = blockIdx.y;
    const int q0 = qt * 128;
    const int b = bh >> 4, h = bh & 15;

    float c[8][4];
#pragma unroll
    for (int i = 0; i < 8; i++)
#pragma unroll
        for (int j = 0; j < 4; j++) c[i][j] = 0.f;

    size_t poff = ((size_t)bh * Ss + q0) * Ss;
    size_t voff = (size_t)bh * HDd * Ss;
    split_mainloop<64, 1, 1, 3>(g_Ph + poff, nullptr, Ss,
                                g_VTh + voff, nullptr, Ss,
                                (qt + 1) * 2, smem, c);

    const int lane = threadIdx.x & 31, wid = threadIdx.x >> 5;
    const int g = lane >> 2, t = lane & 3;
    const int m_base = (wid & 3) * 32, n_base = (wid >> 2) * 32;
#pragma unroll
    for (int mt = 0; mt < 2; mt++)
#pragma unroll
        for (int nt = 0; nt < 4; nt++)
#pragma unroll
            for (int half = 0; half < 2; half++) {
                int m = q0 + m_base + mt * 16 + g + half * 8;
                int d = n_base + nt * 8 + 2 * t;
                __half hx = __float2half_rn(c[mt * 4 + nt][half * 2]);
                __half hy = __float2half_rn(c[mt * 4 + nt][half * 2 + 1]);
                size_t base = ((size_t)b * Ss + m) * Hh + h * 64 + d;
                *(__half2*)(g_Ch + base) = __halves2half2(hx, hy);
            }
}

// ---------------------------------------------------------------------------
// Prep: X fp16 plane; weight transpose (+ lo plane for o_w only).
// ---------------------------------------------------------------------------
__global__ __launch_bounds__(256) void x_conv(const float* __restrict__ hs)
{
    size_t i = ((size_t)blockIdx.x * 256 + threadIdx.x) * 4;
    float4 v = *(const float4*)(hs + i);
    *(__half2*)(g_Xh + i)     = __halves2half2(__float2half_rn(v.x), __float2half_rn(v.y));
    *(__half2*)(g_Xh + i + 2) = __halves2half2(__float2half_rn(v.z), __float2half_rn(v.w));
}

__global__ __launch_bounds__(256) void wt_kernel(
    const float* __restrict__ qw, const float* __restrict__ kw,
    const float* __restrict__ vw, const float* __restrict__ ow)
{
    int w = blockIdx.z;
    const float* W = (w == 0) ? qw : (w == 1) ? kw : (w == 2) ? vw : ow;
    __half* WTh = g_Wh[w];
    __shared__ float t[32][33];
    int n0 = blockIdx.x * 32, k0 = blockIdx.y * 32;
    int tx = threadIdx.x & 31, ty = threadIdx.x >> 5;
#pragma unroll
    for (int i = 0; i < 4; i++)
        t[ty + i * 8][tx] = W[(size_t)(k0 + ty + i * 8) * Hh + n0 + tx];
    __syncthreads();
#pragma unroll
    for (int i = 0; i < 4; i++) {
        float x = t[tx][ty + i * 8];
        __half h, l;
        split_f(x, h, l);
        size_t idx = (size_t)(n0 + ty + i * 8) * Hh + k0 + tx;
        WTh[idx] = h;
        if (w == 3) g_Wl[idx] = l;
    }
}

// ---------------------------------------------------------------------------
// Per-(b,s) gating (1/sqrt(HD) folded)
// ---------------------------------------------------------------------------
__global__ __launch_bounds__(256) void gate_kernel(
    const float* __restrict__ hs, const float* __restrict__ pros,
    const float* __restrict__ pg_w, const float* __restrict__ pg_b,
    const float* __restrict__ mg_w, const float* __restrict__ mg_b)
{
    int bs = blockIdx.x;
    const float* x = hs + (size_t)bs * Hh;
    int tid = threadIdx.x, lane = tid & 31, wrp = tid >> 5;

    float part = 0.f;
    for (int i = tid; i < Hh; i += 256) part += x[i] * mg_w[i];
#pragma unroll
    for (int o = 16; o; o >>= 1) part += __shfl_xor_sync(0xffffffffu, part, o);
    __shared__ float red[8];
    if (lane == 0) red[wrp] = part;
    __syncthreads();
    float tot = 0.f;
#pragma unroll
    for (int w = 0; w < 8; w++) tot += red[w];
    float mem = 1.0f + 0.5f / (1.0f + __expf(-(tot + mg_b[0])));

    if (tid < NHh) {
        const float* p = pros + (size_t)bs * 4;
        float a = p[0] * pg_w[0 * NHh + tid] + p[1] * pg_w[1 * NHh + tid]
                + p[2] * pg_w[2 * NHh + tid] + p[3] * pg_w[3 * NHh + tid]
                + pg_b[tid];
        float pg = 1.0f + 1.0f / (1.0f + __expf(-a));
        g_gain[(size_t)bs * NHh + tid] = pg * mem * 0.125f;
    }
}

// ---------------------------------------------------------------------------
extern "C" void kernel_launch(void* const* d_in, const int* in_sizes, int n_in,
                              void* d_out, int out_size)
{
    const float* hs   = (const float*)d_in[0];
    const float* pros = (const float*)d_in[1];
    const float* q_w  = (const float*)d_in[2];
    const float* q_b  = (const float*)d_in[3];
    const float* k_w  = (const float*)d_in[4];
    const float* k_b  = (const float*)d_in[5];
    const float* v_w  = (const float*)d_in[6];
    const float* v_b  = (const float*)d_in[7];
    const float* o_w  = (const float*)d_in[8];
    const float* o_b  = (const float*)d_in[9];
    const float* pg_w = (const float*)d_in[10];
    const float* pg_b = (const float*)d_in[11];
    const float* mg_w = (const float*)d_in[12];
    const float* mg_b = (const float*)d_in[13];

    float* out  = (float*)d_out;
    float* attn = out + (size_t)Bb * Ss * Hh;

    static cudaStream_t s1 = nullptr, s2 = nullptr;
    static cudaEvent_t evRoot, evWt, evGate, evQ, evV;
    if (!s1) {   // first call = uncaptured correctness run: safe to create
        cudaStreamCreateWithFlags(&s1, cudaStreamNonBlocking);
        cudaStreamCreateWithFlags(&s2, cudaStreamNonBlocking);
        cudaEventCreateWithFlags(&evRoot, cudaEventDisableTiming);
        cudaEventCreateWithFlags(&evWt,   cudaEventDisableTiming);
        cudaEventCreateWithFlags(&evGate, cudaEventDisableTiming);
        cudaEventCreateWithFlags(&evQ,    cudaEventDisableTiming);
        cudaEventCreateWithFlags(&evV,    cudaEventDisableTiming);
        cudaFuncSetAttribute(gemm_qkv,   cudaFuncAttributeMaxDynamicSharedMemorySize, SMEM_QKV);
        cudaFuncSetAttribute(gemm_out,   cudaFuncAttributeMaxDynamicSharedMemorySize, SMEM_OUT);
        cudaFuncSetAttribute(scores_mma, cudaFuncAttributeMaxDynamicSharedMemorySize, SMEM_SC);
        cudaFuncSetAttribute(pv_mma,     cudaFuncAttributeMaxDynamicSharedMemorySize, SMEM_PV);
    }

    // fork: prep kernels in parallel
    cudaEventRecord(evRoot, 0);
    cudaStreamWaitEvent(s1, evRoot, 0);
    cudaStreamWaitEvent(s2, evRoot, 0);

    wt_kernel<<<dim3(32, 32, 4), 256, 0, s1>>>(q_w, k_w, v_w, o_w);
    cudaEventRecord(evWt, s1);

    gate_kernel<<<Bb * Ss, 256, 0, s2>>>(hs, pros, pg_w, pg_b, mg_w, mg_b);
    cudaEventRecord(evGate, s2);

    x_conv<<<(Mtot * Hh) / (256 * 4), 256>>>(hs);

    // join prep into main stream before qkv
    cudaStreamWaitEvent(0, evWt, 0);
    cudaStreamWaitEvent(0, evGate, 0);

    gemm_qkv<<<dim3(8, 32, 3), 256, SMEM_QKV>>>(q_b, k_b, v_b);
    cudaEventRecord(evQ, 0);

    // vt on side stream, overlapped with scores+softmax
    cudaStreamWaitEvent(s1, evQ, 0);
    vt_kernel<<<dim3(64, 2, 32), 256, 0, s1>>>();
    cudaEventRecord(evV, s1);

    scores_mma<<<dim3(16, 16, 32), 256, SMEM_SC>>>(attn);
    softmax_kernel<<<dim3(Ss, NHh, Bb), 256>>>(attn);

    cudaStreamWaitEvent(0, evV, 0);
    pv_mma<<<dim3(16, 32), 256, SMEM_PV>>>();

    gemm_out<<<dim3(8, 32), 256, SMEM_OUT>>>(o_b, out);
}

// round 17
// speedup vs baseline: 1.1108x; 1.0659x over previous
#include <cuda_runtime.h>
#include <cuda_fp16.h>
#include <math.h>
#include <stdint.h>

#define Bb  2
#define Ss  2048
#define Hh  1024
#define NHh 16
#define HDd 64
#define Mtot (Bb * Ss)          // 4096

// ---------------- scratch planes (__device__ globals; no allocs) -----------
__device__ __half g_Xh[(size_t)Mtot * Hh];            // fp16-rounded X
__device__ __half g_Wh[4][(size_t)Hh * Hh];           // transposed weights hi
__device__ __half g_Wl[(size_t)Hh * Hh];              // o_w lo plane only
__device__ __half g_Qh[(size_t)Bb * NHh * Ss * HDd];  // Q hi (gain folded)
__device__ __half g_Kh[(size_t)Bb * NHh * Ss * HDd];
__device__ __half g_Vh[(size_t)Bb * NHh * Ss * HDd];  // V fp16 (pre-rounded)
__device__ __half g_VTh[(size_t)Bb * NHh * HDd * Ss];
__device__ __half g_Ph[(size_t)Bb * NHh * Ss * Ss];   // prob hi plane (pad stays 0)
__device__ __half g_Ch[(size_t)Mtot * Hh];            // fp16 ctx
__device__ float  g_gain[(size_t)Bb * Ss * NHh];
__device__ float  g_sm[(size_t)Bb * NHh * Ss];        // per-row max
__device__ float  g_si[(size_t)Bb * NHh * Ss];        // per-row 1/sum

// ---------------- helpers ---------------------------------------------------
__device__ __forceinline__ uint32_t smem_u32(const void* p) {
    uint32_t a;
    asm("{ .reg .u64 t; cvta.to.shared.u64 t, %1; cvt.u32.u64 %0, t; }" : "=r"(a) : "l"(p));
    return a;
}
__device__ __forceinline__ void split_f(float x, __half& h, __half& l) {
    h = __float2half_rn(x);
    l = __float2half_rn(x - __half2float(h));
}
__device__ __forceinline__ void ldsm4(uint32_t* r, uint32_t addr) {
    asm volatile("ldmatrix.sync.aligned.m8n8.x4.shared.b16 {%0,%1,%2,%3}, [%4];"
        : "=r"(r[0]), "=r"(r[1]), "=r"(r[2]), "=r"(r[3]) : "r"(addr));
}
__device__ __forceinline__ void mma16(float* c, const uint32_t* a, const uint32_t* b) {
    asm volatile("mma.sync.aligned.m16n8k16.row.col.f32.f16.f16.f32 "
        "{%0,%1,%2,%3},{%4,%5,%6,%7},{%8,%9},{%0,%1,%2,%3};"
        : "+f"(c[0]), "+f"(c[1]), "+f"(c[2]), "+f"(c[3])
        : "r"(a[0]), "r"(a[1]), "r"(a[2]), "r"(a[3]), "r"(b[0]), "r"(b[1]));
}
__device__ __forceinline__ void cpa16(uint32_t dst, const void* src) {
    asm volatile("cp.async.cg.shared.global [%0], [%1], 16;" :: "r"(dst), "l"(src));
}
template<int N>
__device__ __forceinline__ void cp_wait() {
    asm volatile("cp.async.wait_group %0;" :: "n"(N < 0 ? 0 : N));
}

// ---------------------------------------------------------------------------
// Split-fp16 tensor-core mainloop (BK=64).
// AP/BP = #planes A/B. NS = pipeline stages, ONE __syncthreads per k-chunk.
// C[128 x BN] += A[128 x 64*nkc] @ Bt[BN x 64*nkc]^T, K-major planes.
// 8 warps: 4 M x 2 N; warp tile = 32 x (BN/2).
// ---------------------------------------------------------------------------
template<int BN, int AP, int BP, int NS>
__device__ __forceinline__ void split_mainloop(
    const __half* __restrict__ Ah, const __half* __restrict__ Al, int ldA,
    const __half* __restrict__ Bh, const __half* __restrict__ Bl, int ldB,
    int nkc, char* smem, float (*cacc)[4])
{
    constexpr int NT = BN / 16;
    constexpr int APL = 128 * 128;       // bytes per A plane
    constexpr int BPL = BN * 128;        // bytes per B plane
    constexpr int BUF = AP * APL + BP * BPL;

    const int tid = threadIdx.x, lane = tid & 31, wid = tid >> 5;
    const int m_base = (wid & 3) * 32;
    const int n_base = (wid >> 2) * (BN / 2);
    uint32_t sbase = smem_u32(smem);

    auto load = [&](int kc, int b) {
        uint32_t s0 = sbase + b * BUF;
        for (int idx = tid; idx < 1024; idx += 256) {
            int row = idx >> 3, ch = idx & 7;
            uint32_t off = row * 128 + ((ch ^ (row & 7)) << 4);
            cpa16(s0 + off, Ah + (size_t)row * ldA + kc * 64 + ch * 8);
            if (AP == 2)
                cpa16(s0 + APL + off, Al + (size_t)row * ldA + kc * 64 + ch * 8);
        }
        for (int idx = tid; idx < BN * 8; idx += 256) {
            int row = idx >> 3, ch = idx & 7;
            uint32_t off = row * 128 + ((ch ^ (row & 7)) << 4);
            cpa16(s0 + AP * APL + off, Bh + (size_t)row * ldB + kc * 64 + ch * 8);
            if (BP == 2)
                cpa16(s0 + AP * APL + BPL + off, Bl + (size_t)row * ldB + kc * 64 + ch * 8);
        }
        asm volatile("cp.async.commit_group;");
    };

#pragma unroll
    for (int s = 0; s < NS - 1; s++)
        if (s < nkc) load(s, s);

    for (int kc = 0; kc < nkc; kc++) {
        int b = kc % NS;
        if (kc + NS - 1 < nkc) cp_wait<NS - 2>();
        else                   cp_wait<0>();
        __syncthreads();
        if (kc + NS - 1 < nkc) load(kc + NS - 1, (kc + NS - 1) % NS);
        uint32_t s0 = sbase + b * BUF;
#pragma unroll
        for (int ks = 0; ks < 4; ks++) {
            uint32_t a[AP][2][4];
            {
                int row = m_base + (lane & 7) + ((lane >> 3) & 1) * 8;
                int ch  = ks * 2 + (lane >> 4);
#pragma unroll
                for (int mt = 0; mt < 2; mt++) {
                    int r2 = row + mt * 16;
                    uint32_t off = r2 * 128 + ((ch ^ (r2 & 7)) << 4);
                    ldsm4(a[0][mt], s0 + off);
                    if (AP == 2) ldsm4(a[1][mt], s0 + APL + off);
                }
            }
            uint32_t bf[BP][NT][2];
            {
                int row = n_base + (lane & 7) + ((lane >> 4) << 3);
                int ch  = ks * 2 + ((lane >> 3) & 1);
#pragma unroll
                for (int np = 0; np < NT / 2; np++) {
                    int r2 = row + np * 16;
                    uint32_t off = r2 * 128 + ((ch ^ (r2 & 7)) << 4);
                    uint32_t t[4];
                    ldsm4(t, s0 + AP * APL + off);
                    bf[0][2 * np][0] = t[0]; bf[0][2 * np][1] = t[1];
                    bf[0][2 * np + 1][0] = t[2]; bf[0][2 * np + 1][1] = t[3];
                    if (BP == 2) {
                        ldsm4(t, s0 + AP * APL + BPL + off);
                        bf[1][2 * np][0] = t[0]; bf[1][2 * np][1] = t[1];
                        bf[1][2 * np + 1][0] = t[2]; bf[1][2 * np + 1][1] = t[3];
                    }
                }
            }
#pragma unroll
            for (int mt = 0; mt < 2; mt++)
#pragma unroll
                for (int nt = 0; nt < NT; nt++) {
                    float* c = cacc[mt * NT + nt];
                    mma16(c, a[0][mt], bf[0][nt]);
                    if (BP == 2) mma16(c, a[0][mt], bf[1][nt]);
                    if (AP == 2) mma16(c, a[1][mt], bf[0][nt]);
                }
        }
    }
}

#define BUF_N128_B1 (128 * 128 + 128 * 128)       // 32 KB
#define BUF_N128_B2 (128 * 128 + 2 * 128 * 128)   // 48 KB
#define BUF_N64_B1  (128 * 128 + 64 * 128)        // 24 KB
#define SMEM_QKV (3 * BUF_N128_B1)                // 96 KB
#define SMEM_OUT (2 * BUF_N128_B2)                // 96 KB
#define SMEM_SC  (BUF_N128_B1)                    // 32 KB (nkc=1)
#define SMEM_PV  (3 * BUF_N64_B1)                 // 72 KB
#define SMEM_ST  (3 * 16384)                      // 48 KB (Q + 2 K buffers)

// ---------------------------------------------------------------------------
// QKV projection (z selects Q/K/V). BM=128, BN=128 (two heads per block).
// ---------------------------------------------------------------------------
__global__ __launch_bounds__(256, 2) void gemm_qkv(
    const float* __restrict__ bq, const float* __restrict__ bk,
    const float* __restrict__ bv)
{
    extern __shared__ char smem[];
    const int z = blockIdx.z;
    const int n0 = blockIdx.x * 128, m0 = blockIdx.y * 128;
    const float* bias = (z == 0) ? bq : (z == 1) ? bk : bv;

    float c[16][4];
#pragma unroll
    for (int i = 0; i < 16; i++)
#pragma unroll
        for (int j = 0; j < 4; j++) c[i][j] = 0.f;

    split_mainloop<128, 1, 1, 3>(g_Xh + (size_t)m0 * Hh, nullptr, Hh,
                                 g_Wh[z] + (size_t)n0 * Hh, nullptr, Hh,
                                 16, smem, c);

    const int lane = threadIdx.x & 31, wid = threadIdx.x >> 5;
    const int g = lane >> 2, t = lane & 3;
    const int m_base = (wid & 3) * 32, n_base = (wid >> 2) * 64;
#pragma unroll
    for (int mt = 0; mt < 2; mt++)
#pragma unroll
        for (int nt = 0; nt < 8; nt++)
#pragma unroll
            for (int half = 0; half < 2; half++) {
                int m = m0 + m_base + mt * 16 + g + half * 8;
                int n = n0 + n_base + nt * 8 + 2 * t;
                float vx = c[mt * 8 + nt][half * 2 + 0] + bias[n];
                float vy = c[mt * 8 + nt][half * 2 + 1] + bias[n + 1];
                int h = n >> 6, d = n & 63;
                int bidx = m >> 11, srow = m & (Ss - 1);
                size_t base = (((size_t)(bidx * NHh + h)) * Ss + srow) * HDd + d;
                if (z == 0) {
                    float gs = g_gain[(size_t)m * NHh + h];
                    vx *= gs; vy *= gs;
                }
                __half2 hv = __halves2half2(__float2half_rn(vx), __float2half_rn(vy));
                __half* dst = (z == 0) ? g_Qh : (z == 1) ? g_Kh : g_Vh;
                *(__half2*)(dst + base) = hv;
            }
}

// ---------------------------------------------------------------------------
// Output projection: fp16 ctx @ o_w + o_b -> d_out[:B*S*H] (fp32). 2 MMAs.
// ---------------------------------------------------------------------------
__global__ __launch_bounds__(256, 2) void gemm_out(
    const float* __restrict__ bias, float* __restrict__ out)
{
    extern __shared__ char smem[];
    const int n0 = blockIdx.x * 128, m0 = blockIdx.y * 128;

    float c[16][4];
#pragma unroll
    for (int i = 0; i < 16; i++)
#pragma unroll
        for (int j = 0; j < 4; j++) c[i][j] = 0.f;

    split_mainloop<128, 1, 2, 2>(g_Ch + (size_t)m0 * Hh, nullptr, Hh,
                                 g_Wh[3] + (size_t)n0 * Hh, g_Wl + (size_t)n0 * Hh, Hh,
                                 16, smem, c);

    const int lane = threadIdx.x & 31, wid = threadIdx.x >> 5;
    const int g = lane >> 2, t = lane & 3;
    const int m_base = (wid & 3) * 32, n_base = (wid >> 2) * 64;
#pragma unroll
    for (int mt = 0; mt < 2; mt++)
#pragma unroll
        for (int nt = 0; nt < 8; nt++)
#pragma unroll
            for (int half = 0; half < 2; half++) {
                int m = m0 + m_base + mt * 16 + g + half * 8;
                int n = n0 + n_base + nt * 8 + 2 * t;
                float2 v = make_float2(c[mt * 8 + nt][half * 2] + bias[n],
                                       c[mt * 8 + nt][half * 2 + 1] + bias[n + 1]);
                *(float2*)(out + (size_t)m * Hh + n) = v;
            }
}

// ---------------------------------------------------------------------------
// Pass 1: per-row softmax stats via online max/sum over recomputed logits.
// grid (bh=32, 16); qt = 15 - blockIdx.y (longest blocks first).
// smem: Q tile 16KB + K double buffer 32KB (dynamic), red arrays static.
// ---------------------------------------------------------------------------
__global__ __launch_bounds__(256, 2) void stats_mma()
{
    extern __shared__ char smem[];
    __shared__ float redM[2][128], redS[2][128];
    const int bh = blockIdx.x;
    const int qt = 15 - blockIdx.y;
    const int q0 = qt * 128;
    const int nkt = qt + 1;

    const int tid = threadIdx.x, lane = tid & 31, wid = tid >> 5;
    const int g = lane >> 2, t = lane & 3;
    const int nw = wid >> 2;
    const int m_base = (wid & 3) * 32, n_base = nw * 64;
    uint32_t sbase = smem_u32(smem);
    const uint32_t sK0 = sbase + 16384;

    // load Q tile (group 0, combined with K0)
    {
        const __half* Qs = g_Qh + ((size_t)bh * Ss + q0) * HDd;
        for (int idx = tid; idx < 1024; idx += 256) {
            int row = idx >> 3, ch = idx & 7;
            cpa16(sbase + row * 128 + ((ch ^ (row & 7)) << 4),
                  Qs + (size_t)row * HDd + ch * 8);
        }
    }
    auto load_k = [&](int kt2, int b) {
        const __half* Ksrc = g_Kh + ((size_t)bh * Ss + kt2 * 128) * HDd;
        uint32_t sK = sK0 + b * 16384;
        for (int idx = tid; idx < 1024; idx += 256) {
            int row = idx >> 3, ch = idx & 7;
            cpa16(sK + row * 128 + ((ch ^ (row & 7)) << 4),
                  Ksrc + (size_t)row * HDd + ch * 8);
        }
        asm volatile("cp.async.commit_group;");
    };
    load_k(0, 0);   // commits Q+K0 together

    float mrow[4], lrow[4];
#pragma unroll
    for (int r = 0; r < 4; r++) { mrow[r] = -INFINITY; lrow[r] = 0.f; }

    for (int kt = 0; kt < nkt; kt++) {
        cp_wait<0>();
        __syncthreads();
        if (kt + 1 < nkt) load_k(kt + 1, (kt + 1) & 1);
        uint32_t sK = sK0 + (kt & 1) * 16384;

        float c[16][4];
#pragma unroll
        for (int i = 0; i < 16; i++)
#pragma unroll
            for (int j = 0; j < 4; j++) c[i][j] = 0.f;

#pragma unroll
        for (int ks = 0; ks < 4; ks++) {
            uint32_t a[2][4];
            {
                int row = m_base + (lane & 7) + ((lane >> 3) & 1) * 8;
                int ch  = ks * 2 + (lane >> 4);
#pragma unroll
                for (int mt = 0; mt < 2; mt++) {
                    int r2 = row + mt * 16;
                    ldsm4(a[mt], sbase + r2 * 128 + ((ch ^ (r2 & 7)) << 4));
                }
            }
            uint32_t bf[8][2];
            {
                int row = n_base + (lane & 7) + ((lane >> 4) << 3);
                int ch  = ks * 2 + ((lane >> 3) & 1);
#pragma unroll
                for (int np = 0; np < 4; np++) {
                    int r2 = row + np * 16;
                    uint32_t tt[4];
                    ldsm4(tt, sK + r2 * 128 + ((ch ^ (r2 & 7)) << 4));
                    bf[2 * np][0] = tt[0]; bf[2 * np][1] = tt[1];
                    bf[2 * np + 1][0] = tt[2]; bf[2 * np + 1][1] = tt[3];
                }
            }
#pragma unroll
            for (int mt = 0; mt < 2; mt++)
#pragma unroll
                for (int nt = 0; nt < 8; nt++)
                    mma16(c[mt * 8 + nt], a[mt], bf[nt]);
        }

        // ---- online stats update ----
        const bool diag = (kt == qt);
        const int k0 = kt * 128;
#pragma unroll
        for (int r = 0; r < 4; r++) {
            int mt = r >> 1, half = r & 1;
            int rowl = m_base + mt * 16 + g + half * 8;
            int gi = q0 + rowl;
            float tm = -INFINITY;
#pragma unroll
            for (int nt = 0; nt < 8; nt++)
#pragma unroll
                for (int e = 0; e < 2; e++) {
                    int gj = k0 + n_base + nt * 8 + 2 * t + e;
                    if (!diag || gj <= gi)
                        tm = fmaxf(tm, c[mt * 8 + nt][half * 2 + e]);
                }
            tm = fmaxf(tm, __shfl_xor_sync(0xffffffffu, tm, 1));
            tm = fmaxf(tm, __shfl_xor_sync(0xffffffffu, tm, 2));
            if (t == 0) redM[nw][rowl] = tm;
        }
        __syncthreads();
        float newm[4];
#pragma unroll
        for (int r = 0; r < 4; r++) {
            int mt = r >> 1, half = r & 1;
            int rowl = m_base + mt * 16 + g + half * 8;
            int gi = q0 + rowl;
            newm[r] = fmaxf(mrow[r], fmaxf(redM[0][rowl], redM[1][rowl]));
            float s = 0.f;
#pragma unroll
            for (int nt = 0; nt < 8; nt++)
#pragma unroll
                for (int e = 0; e < 2; e++) {
                    int gj = k0 + n_base + nt * 8 + 2 * t + e;
                    if (!diag || gj <= gi)
                        s += __expf(c[mt * 8 + nt][half * 2 + e] - newm[r]);
                }
            s += __shfl_xor_sync(0xffffffffu, s, 1);
            s += __shfl_xor_sync(0xffffffffu, s, 2);
            if (t == 0) redS[nw][rowl] = s;
        }
        __syncthreads();
#pragma unroll
        for (int r = 0; r < 4; r++) {
            int mt = r >> 1, half = r & 1;
            int rowl = m_base + mt * 16 + g + half * 8;
            float rowsum = redS[0][rowl] + redS[1][rowl];
            lrow[r] = lrow[r] * __expf(mrow[r] - newm[r]) + rowsum;
            mrow[r] = newm[r];
        }
    }

    if (t == 0 && nw == 0) {
#pragma unroll
        for (int r = 0; r < 4; r++) {
            int mt = r >> 1, half = r & 1;
            int rowl = m_base + mt * 16 + g + half * 8;
            size_t idx = (size_t)bh * Ss + q0 + rowl;
            g_sm[idx] = mrow[r];
            g_si[idx] = 1.0f / lrow[r];
        }
    }
}

// ---------------------------------------------------------------------------
// Pass 2: logits via 1-MMA, then p = exp(v-m)*inv_l written directly:
// fp32 -> attn (d_out), fp16 -> prob plane. Upper tiles zero-fill attn.
// ---------------------------------------------------------------------------
__global__ __launch_bounds__(256, 2) void scores_mma(float* __restrict__ attn)
{
    extern __shared__ char smem[];
    const int kt = blockIdx.x, qt = blockIdx.y, bh = blockIdx.z;
    const int q0 = qt * 128, k0 = kt * 128;
    float* abase = attn + (size_t)bh * Ss * Ss;

    if (kt > qt) {
        float4 z4 = make_float4(0.f, 0.f, 0.f, 0.f);
        for (int idx = threadIdx.x; idx < 128 * 32; idx += 256) {
            int row = idx >> 5, cc = idx & 31;
            *(float4*)(abase + (size_t)(q0 + row) * Ss + k0 + cc * 4) = z4;
        }
        return;
    }

    float c[16][4];
#pragma unroll
    for (int i = 0; i < 16; i++)
#pragma unroll
        for (int j = 0; j < 4; j++) c[i][j] = 0.f;

    size_t qoff = ((size_t)bh * Ss + q0) * HDd;
    size_t koff = ((size_t)bh * Ss + k0) * HDd;
    split_mainloop<128, 1, 1, 2>(g_Qh + qoff, nullptr, HDd,
                                 g_Kh + koff, nullptr, HDd, 1, smem, c);

    const int lane = threadIdx.x & 31, wid = threadIdx.x >> 5;
    const int g = lane >> 2, t = lane & 3;
    const int m_base = (wid & 3) * 32, n_base = (wid >> 2) * 64;
    const bool diag = (kt == qt);
    __half* pbase = g_Ph + (size_t)bh * Ss * Ss;

    float sm_[2][2], si_[2][2];
#pragma unroll
    for (int mt = 0; mt < 2; mt++)
#pragma unroll
        for (int half = 0; half < 2; half++) {
            int gi = q0 + m_base + mt * 16 + g + half * 8;
            size_t sidx = (size_t)bh * Ss + gi;
            sm_[mt][half] = g_sm[sidx];
            si_[mt][half] = g_si[sidx];
        }

#pragma unroll
    for (int mt = 0; mt < 2; mt++)
#pragma unroll
        for (int nt = 0; nt < 8; nt++)
#pragma unroll
            for (int half = 0; half < 2; half++) {
                int gi = q0 + m_base + mt * 16 + g + half * 8;
                int gj = k0 + n_base + nt * 8 + 2 * t;
                float m = sm_[mt][half], il = si_[mt][half];
                float vx = c[mt * 8 + nt][half * 2];
                float vy = c[mt * 8 + nt][half * 2 + 1];
                float px = (diag && gj > gi) ? 0.f : __expf(vx - m) * il;
                float py = (diag && gj + 1 > gi) ? 0.f : __expf(vy - m) * il;
                size_t off = (size_t)gi * Ss + gj;
                *(float2*)(abase + off) = make_float2(px, py);
                *(__half2*)(pbase + off) =
                    __halves2half2(__float2half_rn(px), __float2half_rn(py));
            }
}

// ---------------------------------------------------------------------------
// V transpose: g_Vh[bh][s][d] -> VTh[bh][d][s] (fp16 in/out)
// ---------------------------------------------------------------------------
__global__ __launch_bounds__(256) void vt_kernel()
{
    int bh = blockIdx.z;
    const __half* V = g_Vh + (size_t)bh * Ss * HDd;
    __half* VTh = g_VTh + (size_t)bh * HDd * Ss;
    __shared__ __half t[32][33];
    int s0 = blockIdx.x * 32, d0 = blockIdx.y * 32;
    int tx = threadIdx.x & 31, ty = threadIdx.x >> 5;
#pragma unroll
    for (int i = 0; i < 4; i++)
        t[ty + i * 8][tx] = V[(size_t)(s0 + ty + i * 8) * HDd + d0 + tx];
    __syncthreads();
#pragma unroll
    for (int i = 0; i < 4; i++)
        VTh[(size_t)(d0 + ty + i * 8) * Ss + s0 + tx] = t[tx][ty + i * 8];
}

// ---------------------------------------------------------------------------
// PV: ctx = probs @ V (causal). Single-plane both sides, BK=64, NS=3.
// ---------------------------------------------------------------------------
__global__ __launch_bounds__(256, 2) void pv_mma()
{
    extern __shared__ char smem[];
    const int qt = blockIdx.x, bh = blockIdx.y;
    const int q0 = qt * 128;
    const int b = bh >> 4, h = bh & 15;

    float c[8][4];
#pragma unroll
    for (int i = 0; i < 8; i++)
#pragma unroll
        for (int j = 0; j < 4; j++) c[i][j] = 0.f;

    size_t poff = ((size_t)bh * Ss + q0) * Ss;
    size_t voff = (size_t)bh * HDd * Ss;
    split_mainloop<64, 1, 1, 3>(g_Ph + poff, nullptr, Ss,
                                g_VTh + voff, nullptr, Ss,
                                (qt + 1) * 2, smem, c);

    const int lane = threadIdx.x & 31, wid = threadIdx.x >> 5;
    const int g = lane >> 2, t = lane & 3;
    const int m_base = (wid & 3) * 32, n_base = (wid >> 2) * 32;
#pragma unroll
    for (int mt = 0; mt < 2; mt++)
#pragma unroll
        for (int nt = 0; nt < 4; nt++)
#pragma unroll
            for (int half = 0; half < 2; half++) {
                int m = q0 + m_base + mt * 16 + g + half * 8;
                int d = n_base + nt * 8 + 2 * t;
                __half hx = __float2half_rn(c[mt * 4 + nt][half * 2]);
                __half hy = __float2half_rn(c[mt * 4 + nt][half * 2 + 1]);
                size_t base = ((size_t)b * Ss + m) * Hh + h * 64 + d;
                *(__half2*)(g_Ch + base) = __halves2half2(hx, hy);
            }
}

// ---------------------------------------------------------------------------
// Prep: X fp16 plane; weight transpose (+ lo plane for o_w only).
// ---------------------------------------------------------------------------
__global__ __launch_bounds__(256) void x_conv(const float* __restrict__ hs)
{
    size_t i = ((size_t)blockIdx.x * 256 + threadIdx.x) * 4;
    float4 v = *(const float4*)(hs + i);
    *(__half2*)(g_Xh + i)     = __halves2half2(__float2half_rn(v.x), __float2half_rn(v.y));
    *(__half2*)(g_Xh + i + 2) = __halves2half2(__float2half_rn(v.z), __float2half_rn(v.w));
}

__global__ __launch_bounds__(256) void wt_kernel(
    const float* __restrict__ qw, const float* __restrict__ kw,
    const float* __restrict__ vw, const float* __restrict__ ow)
{
    int w = blockIdx.z;
    const float* W = (w == 0) ? qw : (w == 1) ? kw : (w == 2) ? vw : ow;
    __half* WTh = g_Wh[w];
    __shared__ float t[32][33];
    int n0 = blockIdx.x * 32, k0 = blockIdx.y * 32;
    int tx = threadIdx.x & 31, ty = threadIdx.x >> 5;
#pragma unroll
    for (int i = 0; i < 4; i++)
        t[ty + i * 8][tx] = W[(size_t)(k0 + ty + i * 8) * Hh + n0 + tx];
    __syncthreads();
#pragma unroll
    for (int i = 0; i < 4; i++) {
        float x = t[tx][ty + i * 8];
        __half h, l;
        split_f(x, h, l);
        size_t idx = (size_t)(n0 + ty + i * 8) * Hh + k0 + tx;
        WTh[idx] = h;
        if (w == 3) g_Wl[idx] = l;
    }
}

// ---------------------------------------------------------------------------
// Per-(b,s) gating (1/sqrt(HD) folded)
// ---------------------------------------------------------------------------
__global__ __launch_bounds__(256) void gate_kernel(
    const float* __restrict__ hs, const float* __restrict__ pros,
    const float* __restrict__ pg_w, const float* __restrict__ pg_b,
    const float* __restrict__ mg_w, const float* __restrict__ mg_b)
{
    int bs = blockIdx.x;
    const float* x = hs + (size_t)bs * Hh;
    int tid = threadIdx.x, lane = tid & 31, wrp = tid >> 5;

    float part = 0.f;
    for (int i = tid; i < Hh; i += 256) part += x[i] * mg_w[i];
#pragma unroll
    for (int o = 16; o; o >>= 1) part += __shfl_xor_sync(0xffffffffu, part, o);
    __shared__ float red[8];
    if (lane == 0) red[wrp] = part;
    __syncthreads();
    float tot = 0.f;
#pragma unroll
    for (int w = 0; w < 8; w++) tot += red[w];
    float mem = 1.0f + 0.5f / (1.0f + __expf(-(tot + mg_b[0])));

    if (tid < NHh) {
        const float* p = pros + (size_t)bs * 4;
        float a = p[0] * pg_w[0 * NHh + tid] + p[1] * pg_w[1 * NHh + tid]
                + p[2] * pg_w[2 * NHh + tid] + p[3] * pg_w[3 * NHh + tid]
                + pg_b[tid];
        float pg = 1.0f + 1.0f / (1.0f + __expf(-a));
        g_gain[(size_t)bs * NHh + tid] = pg * mem * 0.125f;
    }
}

// ---------------------------------------------------------------------------
extern "C" void kernel_launch(void* const* d_in, const int* in_sizes, int n_in,
                              void* d_out, int out_size)
{
    const float* hs   = (const float*)d_in[0];
    const float* pros = (const float*)d_in[1];
    const float* q_w  = (const float*)d_in[2];
    const float* q_b  = (const float*)d_in[3];
    const float* k_w  = (const float*)d_in[4];
    const float* k_b  = (const float*)d_in[5];
    const float* v_w  = (const float*)d_in[6];
    const float* v_b  = (const float*)d_in[7];
    const float* o_w  = (const float*)d_in[8];
    const float* o_b  = (const float*)d_in[9];
    const float* pg_w = (const float*)d_in[10];
    const float* pg_b = (const float*)d_in[11];
    const float* mg_w = (const float*)d_in[12];
    const float* mg_b = (const float*)d_in[13];

    float* out  = (float*)d_out;
    float* attn = out + (size_t)Bb * Ss * Hh;

    static cudaStream_t s1 = nullptr, s2 = nullptr;
    static cudaEvent_t evRoot, evWt, evGate, evQ, evV;
    if (!s1) {   // first call = uncaptured correctness run: safe to create
        cudaStreamCreateWithFlags(&s1, cudaStreamNonBlocking);
        cudaStreamCreateWithFlags(&s2, cudaStreamNonBlocking);
        cudaEventCreateWithFlags(&evRoot, cudaEventDisableTiming);
        cudaEventCreateWithFlags(&evWt,   cudaEventDisableTiming);
        cudaEventCreateWithFlags(&evGate, cudaEventDisableTiming);
        cudaEventCreateWithFlags(&evQ,    cudaEventDisableTiming);
        cudaEventCreateWithFlags(&evV,    cudaEventDisableTiming);
        cudaFuncSetAttribute(gemm_qkv,   cudaFuncAttributeMaxDynamicSharedMemorySize, SMEM_QKV);
        cudaFuncSetAttribute(gemm_out,   cudaFuncAttributeMaxDynamicSharedMemorySize, SMEM_OUT);
        cudaFuncSetAttribute(scores_mma, cudaFuncAttributeMaxDynamicSharedMemorySize, SMEM_SC);
        cudaFuncSetAttribute(pv_mma,     cudaFuncAttributeMaxDynamicSharedMemorySize, SMEM_PV);
        cudaFuncSetAttribute(stats_mma,  cudaFuncAttributeMaxDynamicSharedMemorySize, SMEM_ST);
    }

    // fork: prep kernels in parallel
    cudaEventRecord(evRoot, 0);
    cudaStreamWaitEvent(s1, evRoot, 0);
    cudaStreamWaitEvent(s2, evRoot, 0);

    wt_kernel<<<dim3(32, 32, 4), 256, 0, s1>>>(q_w, k_w, v_w, o_w);
    cudaEventRecord(evWt, s1);

    gate_kernel<<<Bb * Ss, 256, 0, s2>>>(hs, pros, pg_w, pg_b, mg_w, mg_b);
    cudaEventRecord(evGate, s2);

    x_conv<<<(Mtot * Hh) / (256 * 4), 256>>>(hs);

    // join prep into main stream before qkv
    cudaStreamWaitEvent(0, evWt, 0);
    cudaStreamWaitEvent(0, evGate, 0);

    gemm_qkv<<<dim3(8, 32, 3), 256, SMEM_QKV>>>(q_b, k_b, v_b);
    cudaEventRecord(evQ, 0);

    // vt on side stream, overlapped with stats+scores
    cudaStreamWaitEvent(s1, evQ, 0);
    vt_kernel<<<dim3(64, 2, 32), 256, 0, s1>>>();
    cudaEventRecord(evV, s1);

    stats_mma<<<dim3(32, 16), 256, SMEM_ST>>>();
    scores_mma<<<dim3(16, 16, 32), 256, SMEM_SC>>>(attn);

    cudaStreamWaitEvent(0, evV, 0);
    pv_mma<<<dim3(16, 32), 256, SMEM_PV>>>();

    gemm_out<<<dim3(8, 32), 256, SMEM_OUT>>>(o_b, out);
}